// round 1
// baseline (speedup 1.0000x reference)
#include <cuda_runtime.h>
#include <cstdint>

// Problem constants (fixed by reference)
#define BATCH   2
#define NPTS    262144
#define CCH     64
#define NBLK    2
#define EPS     1e-5f

#define TJ       128         // permuted positions per CTA tile
#define NTHR     256
#define RSTRIDE  66          // smem row stride in floats (bank-conflict-free for 8-row offsets)

// Shared memory layout (floats)
#define OFF_W    0                       // 12288 floats (one layer's folded weights [i][k][o])
#define OFF_H0   12288                   // (TJ+4)*66 = 8712
#define OFF_H1   (12288 + 8712)          // (TJ+2)*66 = 8580
#define OFF_IN   (12288 + 8712 + 8580)   // (TJ+6)*66 = 8844
#define OFF_PA   (OFF_IN + 8844)         // 134 ints
#define SMEM_FLOATS (OFF_PA + 134 + 256) // +256 pad: slow-path speculative LDS stays in-bounds
#define SMEM_BYTES  (SMEM_FLOATS * 4)

// Scratch (no cudaMalloc allowed)
__device__ float g_mid[(size_t)BATCH * NPTS * CCH];   // inter-block activation
__device__ float g_w[NBLK * 3 * 64 * 3 * 64];         // folded weights, layout [blk][l][i][k][o]
__device__ float g_bias[NBLK * 3 * 64];               // folded bias

// ---------------- packed fp32x2 helpers ----------------
__device__ __forceinline__ unsigned long long pack2(float lo, float hi) {
    unsigned long long r;
    asm("mov.b64 %0, {%1, %2};" : "=l"(r) : "f"(lo), "f"(hi));
    return r;
}
__device__ __forceinline__ void unpack2(unsigned long long v, float& lo, float& hi) {
    asm("mov.b64 {%0, %1}, %2;" : "=f"(lo), "=f"(hi) : "l"(v));
}
__device__ __forceinline__ unsigned long long ffma2(unsigned long long a,
                                                    unsigned long long b,
                                                    unsigned long long c) {
    unsigned long long d;
    asm("fma.rn.f32x2 %0, %1, %2, %3;" : "=l"(d) : "l"(a), "l"(b), "l"(c));
    return d;
}

// ---------------- prep: fold BN into conv weights ----------------
// conv_w: [blk][l][O][I][K]; out g_w: [blk][l][I][K][O] * scale[O]; g_bias = beta - mean*scale
__global__ void prep_kernel(const float* __restrict__ cw, const float* __restrict__ gam,
                            const float* __restrict__ bet, const float* __restrict__ mn,
                            const float* __restrict__ vr) {
    int t = blockIdx.x * blockDim.x + threadIdx.x;
    const int NW = NBLK * 3 * 64 * 3 * 64;
    if (t < NW) {
        int o  = t & 63;
        int t1 = t >> 6;
        int k  = t1 % 3;
        int t2 = t1 / 3;
        int i  = t2 & 63;
        int t3 = t2 >> 6;          // blk*3 + l
        int ch = t3 * 64 + o;
        float sc = gam[ch] * rsqrtf(vr[ch] + EPS);
        g_w[t] = cw[(((size_t)t3 * 64 + o) * 64 + i) * 3 + k] * sc;
    }
    if (t < NBLK * 3 * 64) {
        float sc = gam[t] * rsqrtf(vr[t] + EPS);
        g_bias[t] = bet[t] - mn[t] * sc;
    }
}

// ---------------- conv inner body (templated fast/guarded) ----------------
// Computes 8 positions x 4 channels (pairs ph, ph+16) of one conv layer.
// src rows: out position p reads src[p..p+2] (src carries +1 halo each side).
template<int P, bool FAST>
__device__ __forceinline__ void conv_accum(const float* __restrict__ src,
                                           const unsigned long long* __restrict__ wq,
                                           int base, int ph,
                                           unsigned long long (&a0)[8],
                                           unsigned long long (&a1)[8]) {
    const int lim2 = P + 2 - base;  // valid src rows from base
    for (int i = 0; i < 64; i++) {
        unsigned long long vv[10];
#pragma unroll
        for (int u = 0; u < 10; u++) {
            float t;
            if (FAST) t = src[(base + u) * RSTRIDE + i];
            else      t = (u < lim2) ? src[(base + u) * RSTRIDE + i] : 0.f;
            vv[u] = pack2(t, t);
        }
#pragma unroll
        for (int k = 0; k < 3; k++) {
            unsigned long long w0 = wq[(i * 3 + k) * 32 + ph];
            unsigned long long w1 = wq[(i * 3 + k) * 32 + ph + 16];
#pragma unroll
            for (int u = 0; u < 8; u++) {
                a0[u] = ffma2(w0, vv[u + k], a0[u]);
                a1[u] = ffma2(w1, vv[u + k], a1[u]);
            }
        }
    }
}

// Mid conv layer (layers 0 & 1): relu + zero at global-sequence padding positions.
// Output array index p corresponds to global position j0 - HOFF + p.
template<int P, int HOFF>
__device__ __forceinline__ void conv_mid(const float* __restrict__ src,
                                         float* __restrict__ dst,
                                         const float* __restrict__ s_w,
                                         const float* __restrict__ gb,
                                         int ph, int g, int j0) {
    const unsigned long long* wq = (const unsigned long long*)s_w;
    const unsigned long long blo = pack2(gb[2 * ph],      gb[2 * ph + 1]);
    const unsigned long long bhi = pack2(gb[2 * ph + 32], gb[2 * ph + 33]);
    for (int base = g * 8; base < P; base += 128) {
        unsigned long long a0[8], a1[8];
#pragma unroll
        for (int u = 0; u < 8; u++) { a0[u] = blo; a1[u] = bhi; }

        const bool fast = (base + 8 <= P);
        if (fast) conv_accum<P, true >(src, wq, base, ph, a0, a1);
        else      conv_accum<P, false>(src, wq, base, ph, a0, a1);

        const int lim = P - base;
#pragma unroll
        for (int u = 0; u < 8; u++) {
            if (!fast && u >= lim) break;
            int p = base + u;
            int gpos = j0 - HOFF + p;
            bool valid = (gpos >= 0) && (gpos < NPTS);
            float l0, l1, h0v, h1v;
            unpack2(a0[u], l0, l1);
            unpack2(a1[u], h0v, h1v);
            float2 olo, ohi;
            if (valid) {
                olo = make_float2(fmaxf(l0, 0.f),  fmaxf(l1, 0.f));
                ohi = make_float2(fmaxf(h0v, 0.f), fmaxf(h1v, 0.f));
            } else {
                olo = make_float2(0.f, 0.f);
                ohi = make_float2(0.f, 0.f);
            }
            *(float2*)(dst + p * RSTRIDE + 2 * ph)      = olo;
            *(float2*)(dst + p * RSTRIDE + 2 * ph + 32) = ohi;
        }
    }
}

// Last conv layer: + residual (from s_in) + relu, scatter-store to global out.
__device__ __forceinline__ void conv_last(const float* __restrict__ src,       // s_h1
                                          const float* __restrict__ s_in,
                                          const int* __restrict__ s_pa,
                                          float* __restrict__ xout,
                                          const float* __restrict__ s_w,
                                          const float* __restrict__ gb,
                                          int ph, int g, int j0, int bb) {
    const unsigned long long* wq = (const unsigned long long*)s_w;
    const unsigned long long blo = pack2(gb[2 * ph],      gb[2 * ph + 1]);
    const unsigned long long bhi = pack2(gb[2 * ph + 32], gb[2 * ph + 33]);
    const int base = g * 8;  // P = TJ = 128 exactly: one full-speed iteration per thread
    unsigned long long a0[8], a1[8];
#pragma unroll
    for (int u = 0; u < 8; u++) { a0[u] = blo; a1[u] = bhi; }
    conv_accum<TJ, true>(src, wq, base, ph, a0, a1);

#pragma unroll
    for (int u = 0; u < 8; u++) {
        int p = base + u;
        float l0, l1, h0v, h1v;
        unpack2(a0[u], l0, l1);
        unpack2(a1[u], h0v, h1v);
        // residual: s_in row (p+3) holds global position j0+p
        float2 rlo = *(const float2*)(s_in + (p + 3) * RSTRIDE + 2 * ph);
        float2 rhi = *(const float2*)(s_in + (p + 3) * RSTRIDE + 2 * ph + 32);
        l0  = fmaxf(l0  + rlo.x, 0.f);
        l1  = fmaxf(l1  + rlo.y, 0.f);
        h0v = fmaxf(h0v + rhi.x, 0.f);
        h1v = fmaxf(h1v + rhi.y, 0.f);
        size_t off = ((size_t)bb * NPTS + (size_t)s_pa[p + 3]) * CCH;
        *(float2*)(xout + off + 2 * ph)      = make_float2(l0, l1);
        *(float2*)(xout + off + 2 * ph + 32) = make_float2(h0v, h1v);
    }
}

// ---------------- fused block kernel ----------------
__global__ void __launch_bounds__(NTHR, 1)
block_kernel(const float* __restrict__ xin, float* __restrict__ xout,
             const void* __restrict__ idxp, int blk) {
    extern __shared__ float sm[];
    float* s_w  = sm + OFF_W;
    float* s_h0 = sm + OFF_H0;
    float* s_h1 = sm + OFF_H1;
    float* s_in = sm + OFF_IN;
    int*   s_pa = (int*)(sm + OFF_PA);

    const int tid = threadIdx.x;
    const int bb  = blockIdx.y;
    const int j0  = blockIdx.x * TJ;
    const int ph  = tid & 15;       // channel pair-half: pairs ph and ph+16
    const int g   = tid >> 4;       // position group (16 groups x 8 positions)

    // Detect index dtype (JAX x64 off => int32 despite astype(int64)).
    // int64 layout: every odd 32-bit word is the zero high-half (values < 2^18).
    const unsigned int* iw = (const unsigned int*)idxp;
    const bool is64 = ((iw[1] | iw[3] | iw[5] | iw[7]) == 0u);

    // Stage permutation indices for this tile (+3 halo each side)
    if (tid < TJ + 6) {
        int j = j0 - 3 + tid;
        int v = 0;
        if (j >= 0 && j < NPTS) {
            v = is64 ? (int)((const long long*)idxp)[(size_t)bb * NPTS + j]
                     : ((const int*)idxp)[(size_t)bb * NPTS + j];
        }
        s_pa[tid] = v;
    }
    // Stage layer-0 folded weights
    {
        const float4* w4 = (const float4*)(g_w + (size_t)(blk * 3 + 0) * 12288);
        float4* sw4 = (float4*)s_w;
        for (int e = tid; e < 3072; e += NTHR) sw4[e] = w4[e];
    }
    __syncthreads();

    // Gather input rows through the permutation (zero-pad beyond sequence ends)
    {
        const float2* x2 = (const float2*)xin;
        for (int e = tid; e < (TJ + 6) * 32; e += NTHR) {
            int r = e >> 5, c = e & 31;
            int j = j0 - 3 + r;
            float2 v = make_float2(0.f, 0.f);
            if (j >= 0 && j < NPTS)
                v = x2[((size_t)bb * NPTS + (size_t)s_pa[r]) * 32 + c];
            *(float2*)(s_in + r * RSTRIDE + 2 * c) = v;
        }
    }
    __syncthreads();

    const float* gbias = g_bias + (size_t)blk * 3 * 64;

    // Layer 0: s_in(134 rows) -> s_h0(132 rows), out p <-> gpos j0-2+p
    conv_mid<TJ + 4, 2>(s_in, s_h0, s_w, gbias + 0 * 64, ph, g, j0);
    __syncthreads();
    {   // stage layer-1 weights
        const float4* w4 = (const float4*)(g_w + (size_t)(blk * 3 + 1) * 12288);
        float4* sw4 = (float4*)s_w;
        for (int e = tid; e < 3072; e += NTHR) sw4[e] = w4[e];
    }
    __syncthreads();

    // Layer 1: s_h0(132) -> s_h1(130), out p <-> gpos j0-1+p
    conv_mid<TJ + 2, 1>(s_h0, s_h1, s_w, gbias + 1 * 64, ph, g, j0);
    __syncthreads();
    {   // stage layer-2 weights
        const float4* w4 = (const float4*)(g_w + (size_t)(blk * 3 + 2) * 12288);
        float4* sw4 = (float4*)s_w;
        for (int e = tid; e < 3072; e += NTHR) sw4[e] = w4[e];
    }
    __syncthreads();

    // Layer 2 + residual + relu + scatter
    conv_last(s_h1, s_in, s_pa, xout, s_w, gbias + 2 * 64, ph, g, j0, bb);
}

// ---------------- launch ----------------
extern "C" void kernel_launch(void* const* d_in, const int* in_sizes, int n_in,
                              void* d_out, int out_size) {
    (void)in_sizes; (void)n_in; (void)out_size;
    const float* x    = (const float*)d_in[0];
    const void*  pa1  = d_in[1];
    // d_in[2] = idx_re_1 (unused: re is the inverse of pa, folded into scatter)
    const void*  pa2  = d_in[3];
    // d_in[4] = idx_re_2 (unused)
    const float* cw   = (const float*)d_in[5];
    const float* gam  = (const float*)d_in[6];
    const float* bet  = (const float*)d_in[7];
    const float* mn   = (const float*)d_in[8];
    const float* vr   = (const float*)d_in[9];
    float* out = (float*)d_out;

    float* mid = nullptr;
    cudaGetSymbolAddress((void**)&mid, g_mid);

    static int attr_done = 0;
    if (!attr_done) {
        cudaFuncSetAttribute(block_kernel, cudaFuncAttributeMaxDynamicSharedMemorySize,
                             SMEM_BYTES);
        attr_done = 1;
    }

    prep_kernel<<<(NBLK * 3 * 64 * 3 * 64 + 255) / 256, 256>>>(cw, gam, bet, mn, vr);

    dim3 grid(NPTS / TJ, BATCH);
    block_kernel<<<grid, NTHR, SMEM_BYTES>>>(x,   mid, pa1, 0);
    block_kernel<<<grid, NTHR, SMEM_BYTES>>>(mid, out, pa2, 1);
}

// round 2
// speedup vs baseline: 1.2198x; 1.2198x over previous
#include <cuda_runtime.h>
#include <cstdint>

// Problem constants (fixed by reference)
#define BATCH   2
#define NPTS    262144
#define CCH     64
#define NBLK    2
#define EPS     1e-5f

#define TJ       128         // permuted positions per CTA tile
#define NTHR     256
#define RSTRIDE  66          // smem row stride in floats

// Shared memory layout (floats)
#define OFF_W    0                       // 12288 floats: one layer's folded weights [ipair][k][o][2]
#define OFF_H0   12288                   // 132*66 = 8712
#define OFF_H1   (12288 + 8712)          // 130*66 = 8580
#define OFF_IN   (12288 + 8712 + 8580)   // 134*66 = 8844
#define OFF_PA   (OFF_IN + 8844)         // 134 ints (+pad)
#define SMEM_FLOATS (OFF_PA + 144)
#define SMEM_BYTES  (SMEM_FLOATS * 4)

// Scratch (no cudaMalloc allowed)
__device__ float g_mid[(size_t)BATCH * NPTS * CCH];   // inter-block activation
__device__ float g_w[NBLK * 3 * 64 * 3 * 64];         // folded weights [blk][l][ipair][k][o][2]
__device__ float g_bias[NBLK * 3 * 64];               // folded bias

// ---------------- packed fp32x2 helpers ----------------
__device__ __forceinline__ unsigned long long pack2(float lo, float hi) {
    unsigned long long r;
    asm("mov.b64 %0, {%1, %2};" : "=l"(r) : "f"(lo), "f"(hi));
    return r;
}
__device__ __forceinline__ void unpack2(unsigned long long v, float& lo, float& hi) {
    asm("mov.b64 {%0, %1}, %2;" : "=f"(lo), "=f"(hi) : "l"(v));
}
__device__ __forceinline__ unsigned long long ffma2(unsigned long long a,
                                                    unsigned long long b,
                                                    unsigned long long c) {
    unsigned long long d;
    asm("fma.rn.f32x2 %0, %1, %2, %3;" : "=l"(d) : "l"(a), "l"(b), "l"(c));
    return d;
}

// ---------------- prep: fold BN into conv weights ----------------
// conv_w src: [blk][l][O][I][K].
// dst g_w per layer: [ipair][k][o][d] with i = 2*ipair + d, value w[o][i][k] * scale[o].
__global__ void prep_kernel(const float* __restrict__ cw, const float* __restrict__ gam,
                            const float* __restrict__ bet, const float* __restrict__ mn,
                            const float* __restrict__ vr) {
    int t = blockIdx.x * blockDim.x + threadIdx.x;
    const int NW = NBLK * 3 * 64 * 3 * 64;
    if (t < NW) {
        int within = t % 12288;
        int t3     = t / 12288;      // blk*3 + l
        int d  = within & 1;
        int r  = within >> 1;
        int o  = r & 63;  r >>= 6;
        int k  = r % 3;
        int ip = r / 3;
        int i  = ip * 2 + d;
        int ch = t3 * 64 + o;
        float sc = gam[ch] * rsqrtf(vr[ch] + EPS);
        g_w[t] = cw[(((size_t)t3 * 64 + o) * 64 + i) * 3 + k] * sc;
    }
    if (t < NBLK * 3 * 64) {
        float sc = gam[t] * rsqrtf(vr[t] + EPS);
        g_bias[t] = bet[t] - mn[t] * sc;
    }
}

// ---------------- conv inner body ----------------
// Thread computes U positions x 4 output channels (o = oth + 16*q).
// f32x2 lanes = (even i, odd i) partial sums; activations load as natural LDS.64
// pairs, weights as LDS.64 pairs [ipair][k][o][2]. No duplication MOVs.
template<int U>
__device__ __forceinline__ void conv_body(const float* __restrict__ src,
                                          const unsigned long long* __restrict__ wq,
                                          int base, int oth,
                                          unsigned long long (&acc)[4][9]) {
    for (int ip = 0; ip < 32; ip++) {
        unsigned long long vv[U + 2];
#pragma unroll
        for (int u = 0; u < U + 2; u++)
            vv[u] = *(const unsigned long long*)(src + (base + u) * RSTRIDE + 2 * ip);
#pragma unroll
        for (int k = 0; k < 3; k++) {
#pragma unroll
            for (int q = 0; q < 4; q++) {
                unsigned long long w = wq[(ip * 3 + k) * 64 + oth + 16 * q];
#pragma unroll
                for (int u = 0; u < U; u++)
                    acc[q][u] = ffma2(w, vv[u + k], acc[q][u]);
            }
        }
    }
}

// Mid layer (0 & 1): bias + relu, zero at global-sequence padding positions.
// Output array index p corresponds to global position j0 - HOFF + p.
template<int U, int HOFF>
__device__ __forceinline__ void do_mid(const float* __restrict__ src,
                                       float* __restrict__ dst,
                                       const unsigned long long* __restrict__ wq,
                                       const float* __restrict__ gb,
                                       int base, int oth, int j0) {
    unsigned long long acc[4][9];
#pragma unroll
    for (int q = 0; q < 4; q++) {
        unsigned long long b0 = pack2(gb[oth + 16 * q], 0.f);
#pragma unroll
        for (int u = 0; u < U; u++) acc[q][u] = b0;
    }
    conv_body<U>(src, wq, base, oth, acc);
#pragma unroll
    for (int u = 0; u < U; u++) {
        int p = base + u;
        bool valid = (unsigned)(j0 - HOFF + p) < (unsigned)NPTS;
#pragma unroll
        for (int q = 0; q < 4; q++) {
            float lo, hi;
            unpack2(acc[q][u], lo, hi);
            float s = lo + hi;
            s = valid ? fmaxf(s, 0.f) : 0.f;
            dst[p * RSTRIDE + oth + 16 * q] = s;
        }
    }
}

// Dispatch: P output rows over 16 groups as (P-128) groups of 9 then groups of 8.
// EXTRA is even -> no intra-warp divergence (warp = 2 adjacent groups).
template<int P, int HOFF>
__device__ __forceinline__ void conv_mid(const float* __restrict__ src,
                                         float* __restrict__ dst,
                                         const float* __restrict__ s_w,
                                         const float* __restrict__ gb,
                                         int oth, int g, int j0) {
    const unsigned long long* wq = (const unsigned long long*)s_w;
    constexpr int EXTRA = P - 128;
    if (EXTRA > 0 && g < EXTRA)
        do_mid<9, HOFF>(src, dst, wq, gb, g * 9, oth, j0);
    else
        do_mid<8, HOFF>(src, dst, wq, gb, g * 8 + EXTRA, oth, j0);
}

// Last layer: bias + residual (s_in) + relu, scatter-store to global out.
__device__ __forceinline__ void conv_last(const float* __restrict__ src,     // s_h1
                                          const float* __restrict__ s_in,
                                          const int* __restrict__ s_pa,
                                          float* __restrict__ xout,
                                          const float* __restrict__ s_w,
                                          const float* __restrict__ gb,
                                          int oth, int g, int j0, int bb) {
    const unsigned long long* wq = (const unsigned long long*)s_w;
    const int base = g * 8;            // P = 128 exactly
    unsigned long long acc[4][9];
#pragma unroll
    for (int q = 0; q < 4; q++) {
        unsigned long long b0 = pack2(gb[oth + 16 * q], 0.f);
#pragma unroll
        for (int u = 0; u < 8; u++) acc[q][u] = b0;
    }
    conv_body<8>(src, wq, base, oth, acc);
#pragma unroll
    for (int u = 0; u < 8; u++) {
        int p = base + u;
        size_t off = ((size_t)bb * NPTS + (size_t)s_pa[p + 3]) * CCH;
#pragma unroll
        for (int q = 0; q < 4; q++) {
            int o = oth + 16 * q;
            float lo, hi;
            unpack2(acc[q][u], lo, hi);
            float s = lo + hi + s_in[(p + 3) * RSTRIDE + o];   // residual
            xout[off + o] = fmaxf(s, 0.f);
        }
    }
}

// ---------------- fused block kernel ----------------
__global__ void __launch_bounds__(NTHR, 1)
block_kernel(const float* __restrict__ xin, float* __restrict__ xout,
             const void* __restrict__ idxp, int blk) {
    extern __shared__ float sm[];
    float* s_w  = sm + OFF_W;
    float* s_h0 = sm + OFF_H0;
    float* s_h1 = sm + OFF_H1;
    float* s_in = sm + OFF_IN;
    int*   s_pa = (int*)(sm + OFF_PA);

    const int tid = threadIdx.x;
    const int bb  = blockIdx.y;
    const int j0  = blockIdx.x * TJ;
    const int oth = tid & 15;       // output-channel thread: o = oth + 16*q, q=0..3
    const int g   = tid >> 4;       // position group

    // Detect index dtype (JAX x64 off => int32 despite astype(int64)).
    const unsigned int* iw = (const unsigned int*)idxp;
    const bool is64 = ((iw[1] | iw[3] | iw[5] | iw[7]) == 0u);

    // Stage permutation indices for this tile (+3 halo each side)
    if (tid < TJ + 6) {
        int j = j0 - 3 + tid;
        int v = 0;
        if (j >= 0 && j < NPTS) {
            v = is64 ? (int)((const long long*)idxp)[(size_t)bb * NPTS + j]
                     : ((const int*)idxp)[(size_t)bb * NPTS + j];
        }
        s_pa[tid] = v;
    }
    // Stage layer-0 folded weights
    {
        const float4* w4 = (const float4*)(g_w + (size_t)(blk * 3 + 0) * 12288);
        float4* sw4 = (float4*)s_w;
        for (int e = tid; e < 3072; e += NTHR) sw4[e] = w4[e];
    }
    __syncthreads();

    // Gather input rows through the permutation (zero-pad beyond sequence ends)
    {
        const float2* x2 = (const float2*)xin;
        for (int e = tid; e < (TJ + 6) * 32; e += NTHR) {
            int r = e >> 5, c = e & 31;
            int j = j0 - 3 + r;
            float2 v = make_float2(0.f, 0.f);
            if (j >= 0 && j < NPTS)
                v = x2[((size_t)bb * NPTS + (size_t)s_pa[r]) * 32 + c];
            *(float2*)(s_in + r * RSTRIDE + 2 * c) = v;
        }
    }
    __syncthreads();

    const float* gbias = g_bias + (size_t)blk * 3 * 64;

    // Layer 0: s_in(134 rows) -> s_h0(132 rows), out p <-> gpos j0-2+p
    conv_mid<TJ + 4, 2>(s_in, s_h0, s_w, gbias + 0 * 64, oth, g, j0);
    __syncthreads();
    {   // stage layer-1 weights
        const float4* w4 = (const float4*)(g_w + (size_t)(blk * 3 + 1) * 12288);
        float4* sw4 = (float4*)s_w;
        for (int e = tid; e < 3072; e += NTHR) sw4[e] = w4[e];
    }
    __syncthreads();

    // Layer 1: s_h0(132) -> s_h1(130), out p <-> gpos j0-1+p
    conv_mid<TJ + 2, 1>(s_h0, s_h1, s_w, gbias + 1 * 64, oth, g, j0);
    __syncthreads();
    {   // stage layer-2 weights
        const float4* w4 = (const float4*)(g_w + (size_t)(blk * 3 + 2) * 12288);
        float4* sw4 = (float4*)s_w;
        for (int e = tid; e < 3072; e += NTHR) sw4[e] = w4[e];
    }
    __syncthreads();

    // Layer 2 + residual + relu + scatter
    conv_last(s_h1, s_in, s_pa, xout, s_w, gbias + 2 * 64, oth, g, j0, bb);
}

// ---------------- launch ----------------
extern "C" void kernel_launch(void* const* d_in, const int* in_sizes, int n_in,
                              void* d_out, int out_size) {
    (void)in_sizes; (void)n_in; (void)out_size;
    const float* x    = (const float*)d_in[0];
    const void*  pa1  = d_in[1];
    // d_in[2] = idx_re_1 (unused: re is the inverse of pa, folded into scatter)
    const void*  pa2  = d_in[3];
    // d_in[4] = idx_re_2 (unused)
    const float* cw   = (const float*)d_in[5];
    const float* gam  = (const float*)d_in[6];
    const float* bet  = (const float*)d_in[7];
    const float* mn   = (const float*)d_in[8];
    const float* vr   = (const float*)d_in[9];
    float* out = (float*)d_out;

    float* mid = nullptr;
    cudaGetSymbolAddress((void**)&mid, g_mid);

    static int attr_done = 0;
    if (!attr_done) {
        cudaFuncSetAttribute(block_kernel, cudaFuncAttributeMaxDynamicSharedMemorySize,
                             SMEM_BYTES);
        attr_done = 1;
    }

    prep_kernel<<<(NBLK * 3 * 64 * 3 * 64 + 255) / 256, 256>>>(cw, gam, bet, mn, vr);

    dim3 grid(NPTS / TJ, BATCH);
    block_kernel<<<grid, NTHR, SMEM_BYTES>>>(x,   mid, pa1, 0);
    block_kernel<<<grid, NTHR, SMEM_BYTES>>>(mid, out, pa2, 1);
}

// round 6
// speedup vs baseline: 2.3822x; 1.9530x over previous
#include <cuda_runtime.h>
#include <cuda_bf16.h>
#include <cstdint>

// ---------------- problem constants ----------------
#define BATCH   2
#define NPTS    262144
#define NBLK    2
#define EPS     1e-5f

#define TJ      124                       // valid output rows per tile (M=128 computed)
#define NTILE   ((NPTS + TJ - 1) / TJ)    // 2115
#define NTHR    256
#define ROWS_X  130                       // gathered rows: j0-3 .. j0+126
#define XSTR    68                        // s_x row stride in floats (272B = 17*16: float4-aligned, odd 16B units)

// ---------------- smem byte offsets ----------------
#define SM_PA    0                        // 130 ints
#define SM_BIAS  640                      // 192 floats
#define SM_X     1536                     // 130*68*4 = 35360
#define SM_A0H   36992                    // 128-aligned; 132 rows * 128B = 16896 each
#define SM_A0L   (SM_A0H + 16896)
#define SM_A1H   (SM_A0L + 16896)
#define SM_A1L   (SM_A1H + 16896)
#define SM_W     (SM_A1L + 16896)         // 6 * 8192 = 49152
#define SMEM_BYTES (SM_W + 49152)         // 153728

// ---------------- global scratch (no cudaMalloc) ----------------
__device__ float g_mid[(size_t)BATCH * NPTS * 64];
__device__ unsigned char g_wb[NBLK * 3 * 6 * 8192];   // [b3l][tap*2+prec] 64x64 bf16, swizzled
__device__ float g_bias[NBLK * 3 * 64];

// ---------------- helpers ----------------
__device__ __forceinline__ unsigned smem_u32(const void* p) {
    unsigned a;
    asm("{ .reg .u64 t; cvta.to.shared.u64 t, %1; cvt.u32.u64 %0, t; }" : "=r"(a) : "l"(p));
    return a;
}
__device__ __forceinline__ void ldsm4(unsigned* r, unsigned addr) {
    asm volatile("ldmatrix.sync.aligned.m8n8.x4.shared.b16 {%0,%1,%2,%3}, [%4];"
                 : "=r"(r[0]), "=r"(r[1]), "=r"(r[2]), "=r"(r[3]) : "r"(addr));
}
__device__ __forceinline__ void mma_bf16(float* c, const unsigned* a, const unsigned* b) {
    asm volatile("mma.sync.aligned.m16n8k16.row.col.f32.bf16.bf16.f32 "
                 "{%0,%1,%2,%3}, {%4,%5,%6,%7}, {%8,%9}, {%0,%1,%2,%3};"
                 : "+f"(c[0]), "+f"(c[1]), "+f"(c[2]), "+f"(c[3])
                 : "r"(a[0]), "r"(a[1]), "r"(a[2]), "r"(a[3]), "r"(b[0]), "r"(b[1]));
}
// split (v0,v1) into bf16 hi pair + bf16 lo (residual) pair
__device__ __forceinline__ void cvt_split(float v0, float v1, unsigned& h2, unsigned& l2) {
    asm("cvt.rn.bf16x2.f32 %0, %1, %2;" : "=r"(h2) : "f"(v1), "f"(v0));
    float h0 = __uint_as_float(h2 << 16);
    float h1 = __uint_as_float(h2 & 0xffff0000u);
    float l0 = v0 - h0, l1 = v1 - h1;
    asm("cvt.rn.bf16x2.f32 %0, %1, %2;" : "=r"(l2) : "f"(l1), "f"(l0));
}
__device__ __forceinline__ void sts32(unsigned addr, unsigned v) {
    asm volatile("st.shared.b32 [%0], %1;" :: "r"(addr), "r"(v) : "memory");
}
__device__ __forceinline__ void sts_zero16(unsigned addr) {
    asm volatile("st.shared.v4.b32 [%0], {%1,%1,%1,%1};" :: "r"(addr), "r"(0u) : "memory");
}

// ---------------- prep: fold BN, bf16 hi/lo split, pre-swizzle ----------------
// conv_w src: [blk][l][O][I][K]; image per (b3l, tap, prec): [o row][i col] bf16,
// 128B rows, chunk-swizzle: chunk16 ^= (o & 7).
__global__ void prep_kernel(const float* __restrict__ cw, const float* __restrict__ gam,
                            const float* __restrict__ bet, const float* __restrict__ mn,
                            const float* __restrict__ vr) {
    int t = blockIdx.x * blockDim.x + threadIdx.x;
    const int NW = NBLK * 3 * 3 * 64 * 64;
    if (t < NW) {
        int i   = t & 63;
        int o   = (t >> 6) & 63;
        int tap = (t >> 12) % 3;
        int b3l = t / 12288;
        int ch  = b3l * 64 + o;
        float sc = gam[ch] * rsqrtf(vr[ch] + EPS);
        float v  = cw[(((size_t)b3l * 64 + o) * 64 + i) * 3 + tap] * sc;
        __nv_bfloat16 hi = __float2bfloat16_rn(v);
        float lof = v - __bfloat162float(hi);
        __nv_bfloat16 lo = __float2bfloat16_rn(lof);
        unsigned off = (unsigned)(o * 128 + (((i >> 3) ^ (o & 7)) << 4) + ((i & 7) << 1));
        size_t ib = (size_t)(b3l * 6 + tap * 2) * 8192;
        *(unsigned short*)(g_wb + ib + off)        = __bfloat16_as_ushort(hi);
        *(unsigned short*)(g_wb + ib + 8192 + off) = __bfloat16_as_ushort(lo);
    }
    if (t < NBLK * 3 * 64) {
        float sc = gam[t] * rsqrtf(vr[t] + EPS);
        g_bias[t] = bet[t] - mn[t] * sc;
    }
}

// ---------------- fused block kernel ----------------
__global__ void __launch_bounds__(NTHR, 1)
block_kernel(const float* __restrict__ xin, float* __restrict__ xout,
             const void* __restrict__ idxp, int blk) {
    extern __shared__ char smem[];
    const unsigned sbase = smem_u32(smem);
    const int tid = threadIdx.x;
    const int w   = tid >> 5;
    const int lid = tid & 31;
    const int bb  = blockIdx.y;
    const int j0  = blockIdx.x * TJ;

    int*   s_pa   = (int*)(smem + SM_PA);
    float* s_bias = (float*)(smem + SM_BIAS);
    float* s_x    = (float*)(smem + SM_X);

    // index dtype detect (JAX x64 off => int32 despite astype(int64))
    const unsigned* iw = (const unsigned*)idxp;
    const bool is64 = ((iw[1] | iw[3] | iw[5] | iw[7]) == 0u);

    if (tid < ROWS_X) {                          // pa rows j0-3 .. j0+126
        int j = j0 - 3 + tid;
        int v = 0;
        if (j >= 0 && j < NPTS)
            v = is64 ? (int)((const long long*)idxp)[(size_t)bb * NPTS + j]
                     : ((const int*)idxp)[(size_t)bb * NPTS + j];
        s_pa[tid] = v;
    }
    if (tid < 192) s_bias[tid] = g_bias[blk * 192 + tid];
    {   // stage layer-0 weights (48KB, pre-swizzled)
        const uint4* src = (const uint4*)(g_wb + (size_t)(blk * 3) * 49152);
        uint4* dst = (uint4*)(smem + SM_W);
        for (int e = tid; e < 3072; e += NTHR) dst[e] = src[e];
    }
    __syncthreads();

    // gather x through the permutation: fp32 copy + bf16 hi/lo tiles
    {
        const float4* x4 = (const float4*)xin;
        for (int e = tid; e < ROWS_X * 16; e += NTHR) {
            int r = e >> 4, c4 = e & 15;
            int j = j0 - 3 + r;
            float4 v = make_float4(0.f, 0.f, 0.f, 0.f);
            if (j >= 0 && j < NPTS)
                v = x4[((size_t)bb * NPTS + (size_t)s_pa[r]) * 16 + c4];
            *(float4*)(s_x + r * XSTR + c4 * 4) = v;
            unsigned h01, l01, h23, l23;
            cvt_split(v.x, v.y, h01, l01);
            cvt_split(v.z, v.w, h23, l23);
            unsigned off = (unsigned)(r * 128 + ((((unsigned)c4 >> 1) ^ (r & 7)) << 4) + ((c4 & 1) << 3));
            *(uint2*)(smem + SM_A0H + off) = make_uint2(h01, h23);
            *(uint2*)(smem + SM_A0L + off) = make_uint2(l01, l23);
        }
        if (tid < 32) {   // zero tail rows 130,131 of both buffer pairs
            int rr = 130 + (lid >> 4), ch = lid & 7, pr = (lid >> 3) & 1;
            unsigned off = (unsigned)(rr * 128 + ch * 16);
            sts_zero16(sbase + (pr ? SM_A0L : SM_A0H) + off);
            sts_zero16(sbase + (pr ? SM_A1L : SM_A1H) + off);
        }
    }
    __syncthreads();

    const int wm  = (w & 3) * 32;      // warp m-base (rows)
    const int wn  = (w >> 2) * 32;     // warp n-base (out channels)
    const int grp = lid >> 2;          // fragment row group
    const int qd  = lid & 3;           // fragment col quad

    for (int l = 0; l < 3; l++) {
        const unsigned inH  = sbase + ((l & 1) ? SM_A1H : SM_A0H);
        const unsigned inL  = sbase + ((l & 1) ? SM_A1L : SM_A0L);
        const unsigned outH = sbase + ((l & 1) ? SM_A0H : SM_A1H);
        const unsigned outL = sbase + ((l & 1) ? SM_A0L : SM_A1L);
        const unsigned sW   = sbase + SM_W;

        float c[8][4];                 // [mt*4+nt][4]
#pragma unroll
        for (int nt = 0; nt < 4; nt++) {
            int cb = wn + nt * 8 + 2 * qd;
            float b0 = s_bias[l * 64 + cb], b1 = s_bias[l * 64 + cb + 1];
#pragma unroll
            for (int mt = 0; mt < 2; mt++) {
                c[mt * 4 + nt][0] = b0; c[mt * 4 + nt][1] = b1;
                c[mt * 4 + nt][2] = b0; c[mt * 4 + nt][3] = b1;
            }
        }

        const int lrow = ((lid >> 3) & 1) * 8 + (lid & 7);   // row within 16-block
        const int lch  = lid >> 4;                           // chunk select (0/1)

        for (int tap = 0; tap < 3; tap++) {
            const unsigned wtH = sW + (unsigned)(tap * 2) * 8192;
            const unsigned wtL = wtH + 8192;
#pragma unroll
            for (int kc = 0; kc < 4; kc++) {
                unsigned ah[2][4], al[2][4];
#pragma unroll
                for (int mt = 0; mt < 2; mt++) {
                    int R  = wm + mt * 16 + tap + lrow;
                    int CH = 2 * kc + lch;
                    unsigned off = (unsigned)(R * 128 + ((CH ^ (R & 7)) << 4));
                    ldsm4(ah[mt], inH + off);
                    ldsm4(al[mt], inL + off);
                }
                unsigned bh[4][2], bl[4][2];
#pragma unroll
                for (int g = 0; g < 2; g++) {
                    int O  = wn + g * 16 + lrow;
                    int CH = 2 * kc + lch;
                    unsigned off = (unsigned)(O * 128 + ((CH ^ (O & 7)) << 4));
                    unsigned r4[4];
                    ldsm4(r4, wtH + off);
                    bh[g * 2][0] = r4[0]; bh[g * 2][1] = r4[2];
                    bh[g * 2 + 1][0] = r4[1]; bh[g * 2 + 1][1] = r4[3];
                    ldsm4(r4, wtL + off);
                    bl[g * 2][0] = r4[0]; bl[g * 2][1] = r4[2];
                    bl[g * 2 + 1][0] = r4[1]; bl[g * 2 + 1][1] = r4[3];
                }
#pragma unroll
                for (int mt = 0; mt < 2; mt++)
#pragma unroll
                    for (int nt = 0; nt < 4; nt++) {
                        mma_bf16(c[mt * 4 + nt], ah[mt], bh[nt]);   // Ah*Wh
                        mma_bf16(c[mt * 4 + nt], al[mt], bh[nt]);   // Al*Wh
                        mma_bf16(c[mt * 4 + nt], ah[mt], bl[nt]);   // Ah*Wl
                    }
            }
        }

        if (l < 2) {
            // ---- mid epilogue: relu + boundary zero, bf16 hi/lo -> out buffers ----
#pragma unroll
            for (int mt = 0; mt < 2; mt++)
#pragma unroll
                for (int h = 0; h < 2; h++) {
                    int row = wm + mt * 16 + h * 8 + grp;
                    int pos = j0 - 2 + l + row;
                    bool valid = (unsigned)pos < (unsigned)NPTS;
#pragma unroll
                    for (int nt = 0; nt < 4; nt++) {
                        float v0 = c[mt * 4 + nt][h * 2];
                        float v1 = c[mt * 4 + nt][h * 2 + 1];
                        v0 = valid ? fmaxf(v0, 0.f) : 0.f;
                        v1 = valid ? fmaxf(v1, 0.f) : 0.f;
                        unsigned h2, l2;
                        cvt_split(v0, v1, h2, l2);
                        int cb = wn + nt * 8 + 2 * qd;
                        unsigned off = (unsigned)(row * 128 + (((cb >> 3) ^ (row & 7)) << 4) + ((cb & 7) << 1));
                        sts32(outH + off, h2);
                        sts32(outL + off, l2);
                    }
                }
            if (tid < 32) {   // zero rows 128,129 of the buffer just written
                int rr = 128 + (lid >> 4), ch = lid & 7, pr = (lid >> 3) & 1;
                unsigned off = (unsigned)(rr * 128 + ch * 16);
                sts_zero16((pr ? outL : outH) + off);
            }
            __syncthreads();
            {   // stage next layer's weights
                const uint4* src = (const uint4*)(g_wb + (size_t)(blk * 3 + l + 1) * 49152);
                uint4* dst = (uint4*)(smem + SM_W);
                for (int e = tid; e < 3072; e += NTHR) dst[e] = src[e];
            }
            __syncthreads();
        } else {
            // ---- final epilogue: + residual(fp32) + relu, scatter-store ----
#pragma unroll
            for (int mt = 0; mt < 2; mt++)
#pragma unroll
                for (int h = 0; h < 2; h++) {
                    int row = wm + mt * 16 + h * 8 + grp;
                    if (row >= TJ) continue;
                    int pos = j0 + row;
                    if (pos >= NPTS) continue;
                    size_t obase = ((size_t)bb * NPTS + (size_t)s_pa[row + 3]) * 64;
#pragma unroll
                    for (int nt = 0; nt < 4; nt++) {
                        int cb = wn + nt * 8 + 2 * qd;
                        float2 xr = *(const float2*)(s_x + (row + 3) * XSTR + cb);
                        float v0 = fmaxf(c[mt * 4 + nt][h * 2]     + xr.x, 0.f);
                        float v1 = fmaxf(c[mt * 4 + nt][h * 2 + 1] + xr.y, 0.f);
                        *(float2*)(xout + obase + cb) = make_float2(v0, v1);
                    }
                }
        }
    }
}

// ---------------- launch ----------------
extern "C" void kernel_launch(void* const* d_in, const int* in_sizes, int n_in,
                              void* d_out, int out_size) {
    (void)in_sizes; (void)n_in; (void)out_size;
    const float* x   = (const float*)d_in[0];
    const void*  pa1 = d_in[1];
    // d_in[2] = idx_re_1 (unused: re is the inverse of pa, folded into scatter)
    const void*  pa2 = d_in[3];
    // d_in[4] = idx_re_2 (unused)
    const float* cw  = (const float*)d_in[5];
    const float* gam = (const float*)d_in[6];
    const float* bet = (const float*)d_in[7];
    const float* mn  = (const float*)d_in[8];
    const float* vr  = (const float*)d_in[9];
    float* out = (float*)d_out;

    float* mid = nullptr;
    cudaGetSymbolAddress((void**)&mid, g_mid);

    static int attr_done = 0;
    if (!attr_done) {
        cudaFuncSetAttribute(block_kernel, cudaFuncAttributeMaxDynamicSharedMemorySize,
                             SMEM_BYTES);
        attr_done = 1;
    }

    const int NPREP = NBLK * 3 * 3 * 64 * 64;
    prep_kernel<<<(NPREP + 255) / 256, 256>>>(cw, gam, bet, mn, vr);

    dim3 grid(NTILE, BATCH);
    block_kernel<<<grid, NTHR, SMEM_BYTES>>>(x,   mid, pa1, 0);
    block_kernel<<<grid, NTHR, SMEM_BYTES>>>(mid, out, pa2, 1);
}

// round 7
// speedup vs baseline: 3.3191x; 1.3933x over previous
#include <cuda_runtime.h>
#include <cuda_bf16.h>
#include <cstdint>

// ---------------- problem constants ----------------
#define BATCH   2
#define NPTS    262144
#define NBLK    2
#define EPS     1e-5f

#define TJ      124                       // valid output rows per tile (M=128 computed)
#define NTILE   ((NPTS + TJ - 1) / TJ)    // 2115
#define NTHR    512
#define ROWS_X  130                       // gathered rows: j0-3 .. j0+126
#define XSTR    68                        // s_x row stride in floats (272B = 17*16)

// ---------------- smem byte offsets ----------------
#define SM_PA    0                        // 130 ints
#define SM_BIAS  640                      // 192 floats
#define SM_X     1536                     // 130*68*4 = 35360
#define SM_A0H   36992                    // 128-aligned; 132 rows * 128B = 16896 each
#define SM_A0L   (SM_A0H + 16896)
#define SM_A1H   (SM_A0L + 16896)
#define SM_A1L   (SM_A1H + 16896)
#define SM_W0    (SM_A1L + 16896)         // 104576; 48KB weight buffer 0
#define SM_W1    (SM_W0 + 49152)          // 153728; 48KB weight buffer 1
#define SMEM_BYTES (SM_W1 + 49152)        // 202880

// ---------------- global scratch (no cudaMalloc) ----------------
__device__ float g_mid[(size_t)BATCH * NPTS * 64];
__device__ unsigned char g_wb[NBLK * 3 * 6 * 8192];   // [b3l][tap*2+prec] 64x64 bf16, swizzled
__device__ float g_bias[NBLK * 3 * 64];

// ---------------- helpers ----------------
__device__ __forceinline__ unsigned smem_u32(const void* p) {
    unsigned a;
    asm("{ .reg .u64 t; cvta.to.shared.u64 t, %1; cvt.u32.u64 %0, t; }" : "=r"(a) : "l"(p));
    return a;
}
__device__ __forceinline__ void ldsm4(unsigned* r, unsigned addr) {
    asm volatile("ldmatrix.sync.aligned.m8n8.x4.shared.b16 {%0,%1,%2,%3}, [%4];"
                 : "=r"(r[0]), "=r"(r[1]), "=r"(r[2]), "=r"(r[3]) : "r"(addr));
}
__device__ __forceinline__ void mma_bf16(float* c, const unsigned* a, const unsigned* b) {
    asm volatile("mma.sync.aligned.m16n8k16.row.col.f32.bf16.bf16.f32 "
                 "{%0,%1,%2,%3}, {%4,%5,%6,%7}, {%8,%9}, {%0,%1,%2,%3};"
                 : "+f"(c[0]), "+f"(c[1]), "+f"(c[2]), "+f"(c[3])
                 : "r"(a[0]), "r"(a[1]), "r"(a[2]), "r"(a[3]), "r"(b[0]), "r"(b[1]));
}
// split (v0,v1) into bf16 hi pair + bf16 lo (residual) pair
__device__ __forceinline__ void cvt_split(float v0, float v1, unsigned& h2, unsigned& l2) {
    asm("cvt.rn.bf16x2.f32 %0, %1, %2;" : "=r"(h2) : "f"(v1), "f"(v0));
    float h0 = __uint_as_float(h2 << 16);
    float h1 = __uint_as_float(h2 & 0xffff0000u);
    float l0 = v0 - h0, l1 = v1 - h1;
    asm("cvt.rn.bf16x2.f32 %0, %1, %2;" : "=r"(l2) : "f"(l1), "f"(l0));
}
__device__ __forceinline__ void sts32(unsigned addr, unsigned v) {
    asm volatile("st.shared.b32 [%0], %1;" :: "r"(addr), "r"(v) : "memory");
}
__device__ __forceinline__ void sts_zero16(unsigned addr) {
    asm volatile("st.shared.v4.b32 [%0], {%1,%1,%1,%1};" :: "r"(addr), "r"(0u) : "memory");
}
// async 48KB weight image copy (3072 x 16B) + commit one group
__device__ __forceinline__ void weights_async(unsigned dst, const unsigned char* src, int tid) {
    for (int e = tid; e < 3072; e += NTHR)
        asm volatile("cp.async.cg.shared.global [%0], [%1], 16;"
                     :: "r"(dst + e * 16), "l"(src + (size_t)e * 16) : "memory");
    asm volatile("cp.async.commit_group;" ::: "memory");
}
#define CP_WAIT(n) asm volatile("cp.async.wait_group %0;" :: "n"(n) : "memory")

// ---------------- prep: fold BN, bf16 hi/lo split, pre-swizzle ----------------
// conv_w src: [blk][l][O][I][K]; image per (b3l, tap, prec): [o row][i col] bf16,
// 128B rows, chunk-swizzle: chunk16 ^= (o & 7).
__global__ void prep_kernel(const float* __restrict__ cw, const float* __restrict__ gam,
                            const float* __restrict__ bet, const float* __restrict__ mn,
                            const float* __restrict__ vr) {
    int t = blockIdx.x * blockDim.x + threadIdx.x;
    const int NW = NBLK * 3 * 3 * 64 * 64;
    if (t < NW) {
        int i   = t & 63;
        int o   = (t >> 6) & 63;
        int tap = (t >> 12) % 3;
        int b3l = t / 12288;
        int ch  = b3l * 64 + o;
        float sc = gam[ch] * rsqrtf(vr[ch] + EPS);
        float v  = cw[(((size_t)b3l * 64 + o) * 64 + i) * 3 + tap] * sc;
        __nv_bfloat16 hi = __float2bfloat16_rn(v);
        float lof = v - __bfloat162float(hi);
        __nv_bfloat16 lo = __float2bfloat16_rn(lof);
        unsigned off = (unsigned)(o * 128 + (((i >> 3) ^ (o & 7)) << 4) + ((i & 7) << 1));
        size_t ib = (size_t)(b3l * 6 + tap * 2) * 8192;
        *(unsigned short*)(g_wb + ib + off)        = __bfloat16_as_ushort(hi);
        *(unsigned short*)(g_wb + ib + 8192 + off) = __bfloat16_as_ushort(lo);
    }
    if (t < NBLK * 3 * 64) {
        float sc = gam[t] * rsqrtf(vr[t] + EPS);
        g_bias[t] = bet[t] - mn[t] * sc;
    }
}

// ---------------- fused block kernel ----------------
__global__ void __launch_bounds__(NTHR, 1)
block_kernel(const float* __restrict__ xin, float* __restrict__ xout,
             const void* __restrict__ idxp, int blk) {
    extern __shared__ char smem[];
    const unsigned sbase = smem_u32(smem);
    const int tid = threadIdx.x;
    const int w   = tid >> 5;
    const int lid = tid & 31;
    const int bb  = blockIdx.y;
    const int j0  = blockIdx.x * TJ;

    int*   s_pa   = (int*)(smem + SM_PA);
    float* s_bias = (float*)(smem + SM_BIAS);
    float* s_x    = (float*)(smem + SM_X);

    // index dtype detect (JAX x64 off => int32 despite astype(int64))
    const unsigned* iw = (const unsigned*)idxp;
    const bool is64 = ((iw[1] | iw[3] | iw[5] | iw[7]) == 0u);

    if (tid < ROWS_X) {                          // pa rows j0-3 .. j0+126
        int j = j0 - 3 + tid;
        int v = 0;
        if (j >= 0 && j < NPTS)
            v = is64 ? (int)((const long long*)idxp)[(size_t)bb * NPTS + j]
                     : ((const int*)idxp)[(size_t)bb * NPTS + j];
        s_pa[tid] = v;
    }
    if (tid < 192) s_bias[tid] = g_bias[blk * 192 + tid];

    // async weight staging: G0 = layer0 -> W0, G1 = layer1 -> W1 (overlaps gather)
    weights_async(sbase + SM_W0, g_wb + (size_t)(blk * 3 + 0) * 49152, tid);
    weights_async(sbase + SM_W1, g_wb + (size_t)(blk * 3 + 1) * 49152, tid);
    __syncthreads();                             // s_pa visible for gather

    // gather x through the permutation: fp32 copy + bf16 hi/lo tiles
    {
        const float4* x4 = (const float4*)xin;
        for (int e = tid; e < ROWS_X * 16; e += NTHR) {
            int r = e >> 4, c4 = e & 15;
            int j = j0 - 3 + r;
            float4 v = make_float4(0.f, 0.f, 0.f, 0.f);
            if (j >= 0 && j < NPTS)
                v = x4[((size_t)bb * NPTS + (size_t)s_pa[r]) * 16 + c4];
            *(float4*)(s_x + r * XSTR + c4 * 4) = v;
            unsigned h01, l01, h23, l23;
            cvt_split(v.x, v.y, h01, l01);
            cvt_split(v.z, v.w, h23, l23);
            unsigned off = (unsigned)(r * 128 + ((((unsigned)c4 >> 1) ^ (r & 7)) << 4) + ((c4 & 1) << 3));
            *(uint2*)(smem + SM_A0H + off) = make_uint2(h01, h23);
            *(uint2*)(smem + SM_A0L + off) = make_uint2(l01, l23);
        }
        if (tid < 32) {   // zero tail rows 130,131 of both buffer pairs
            int rr = 130 + (lid >> 4), ch = lid & 7, pr = (lid >> 3) & 1;
            unsigned off = (unsigned)(rr * 128 + ch * 16);
            sts_zero16(sbase + (pr ? SM_A0L : SM_A0H) + off);
            sts_zero16(sbase + (pr ? SM_A1L : SM_A1H) + off);
        }
    }
    CP_WAIT(1);                                  // G0 (layer0 weights) landed
    __syncthreads();

    // 16 warps: 4 m-groups x 4 n-groups; warp tile 32 rows x 16 cols
    const int wm  = (w & 3) * 32;
    const int wn  = (w >> 2) * 16;
    const int grp = lid >> 2;          // fragment row group
    const int qd  = lid & 3;           // fragment col quad
    const int lrow = ((lid >> 3) & 1) * 8 + (lid & 7);   // ldsm row within 16-block
    const int lch  = lid >> 4;                           // ldsm chunk select (0/1)

    for (int l = 0; l < 3; l++) {
        const unsigned inH  = sbase + ((l & 1) ? SM_A1H : SM_A0H);
        const unsigned inL  = sbase + ((l & 1) ? SM_A1L : SM_A0L);
        const unsigned outH = sbase + ((l & 1) ? SM_A0H : SM_A1H);
        const unsigned outL = sbase + ((l & 1) ? SM_A0L : SM_A1L);
        const unsigned sW   = sbase + ((l == 1) ? SM_W1 : SM_W0);

        if (l == 1)   // G2 = layer2 -> W0 (W0 free: layer0 done), overlaps layer1 MMA
            weights_async(sbase + SM_W0, g_wb + (size_t)(blk * 3 + 2) * 49152, tid);

        float c[2][2][4];              // [mt][nt][frag]
#pragma unroll
        for (int nt = 0; nt < 2; nt++) {
            int cb = wn + nt * 8 + 2 * qd;
            float b0 = s_bias[l * 64 + cb], b1 = s_bias[l * 64 + cb + 1];
#pragma unroll
            for (int mt = 0; mt < 2; mt++) {
                c[mt][nt][0] = b0; c[mt][nt][1] = b1;
                c[mt][nt][2] = b0; c[mt][nt][3] = b1;
            }
        }

#pragma unroll
        for (int tap = 0; tap < 3; tap++) {
            const unsigned wtH = sW + (unsigned)(tap * 2) * 8192;
            const unsigned wtL = wtH + 8192;
#pragma unroll
            for (int kc = 0; kc < 4; kc++) {
                const int CH = 2 * kc + lch;
                unsigned ah[2][4], al[2][4];
#pragma unroll
                for (int mt = 0; mt < 2; mt++) {
                    int R  = wm + mt * 16 + tap + lrow;
                    unsigned off = (unsigned)(R * 128 + ((CH ^ (R & 7)) << 4));
                    ldsm4(ah[mt], inH + off);
                    ldsm4(al[mt], inL + off);
                }
                // B: one x4 per precision covers n16 x k16
                unsigned bh[2][2], bl[2][2];
                {
                    int O  = wn + lrow;
                    unsigned off = (unsigned)(O * 128 + ((CH ^ (O & 7)) << 4));
                    unsigned r4[4];
                    ldsm4(r4, wtH + off);
                    bh[0][0] = r4[0]; bh[0][1] = r4[2];
                    bh[1][0] = r4[1]; bh[1][1] = r4[3];
                    ldsm4(r4, wtL + off);
                    bl[0][0] = r4[0]; bl[0][1] = r4[2];
                    bl[1][0] = r4[1]; bl[1][1] = r4[3];
                }
#pragma unroll
                for (int mt = 0; mt < 2; mt++)
#pragma unroll
                    for (int nt = 0; nt < 2; nt++) {
                        mma_bf16(c[mt][nt], ah[mt], bh[nt]);   // Ah*Wh
                        mma_bf16(c[mt][nt], al[mt], bh[nt]);   // Al*Wh
                        mma_bf16(c[mt][nt], ah[mt], bl[nt]);   // Ah*Wl
                    }
            }
        }

        if (l < 2) {
            // ---- mid epilogue: relu + boundary zero, bf16 hi/lo -> out buffers ----
#pragma unroll
            for (int mt = 0; mt < 2; mt++)
#pragma unroll
                for (int h = 0; h < 2; h++) {
                    int row = wm + mt * 16 + h * 8 + grp;
                    int pos = j0 - 2 + l + row;
                    bool valid = (unsigned)pos < (unsigned)NPTS;
#pragma unroll
                    for (int nt = 0; nt < 2; nt++) {
                        float v0 = c[mt][nt][h * 2];
                        float v1 = c[mt][nt][h * 2 + 1];
                        v0 = valid ? fmaxf(v0, 0.f) : 0.f;
                        v1 = valid ? fmaxf(v1, 0.f) : 0.f;
                        unsigned h2, l2;
                        cvt_split(v0, v1, h2, l2);
                        int cb = wn + nt * 8 + 2 * qd;
                        unsigned off = (unsigned)(row * 128 + (((cb >> 3) ^ (row & 7)) << 4) + ((cb & 7) << 1));
                        sts32(outH + off, h2);
                        sts32(outL + off, l2);
                    }
                }
            if (tid < 32) {   // zero rows 128,129 of the buffer just written
                int rr = 128 + (lid >> 4), ch = lid & 7, pr = (lid >> 3) & 1;
                unsigned off = (unsigned)(rr * 128 + ch * 16);
                sts_zero16((pr ? outL : outH) + off);
            }
            CP_WAIT(0);       // next layer's weights landed
            __syncthreads();
        } else {
            // ---- final epilogue: + residual(fp32) + relu, scatter-store ----
#pragma unroll
            for (int mt = 0; mt < 2; mt++)
#pragma unroll
                for (int h = 0; h < 2; h++) {
                    int row = wm + mt * 16 + h * 8 + grp;
                    if (row >= TJ) continue;
                    int pos = j0 + row;
                    if (pos >= NPTS) continue;
                    size_t obase = ((size_t)bb * NPTS + (size_t)s_pa[row + 3]) * 64;
#pragma unroll
                    for (int nt = 0; nt < 2; nt++) {
                        int cb = wn + nt * 8 + 2 * qd;
                        float2 xr = *(const float2*)(s_x + (row + 3) * XSTR + cb);
                        float v0 = fmaxf(c[mt][nt][h * 2]     + xr.x, 0.f);
                        float v1 = fmaxf(c[mt][nt][h * 2 + 1] + xr.y, 0.f);
                        *(float2*)(xout + obase + cb) = make_float2(v0, v1);
                    }
                }
        }
    }
}

// ---------------- launch ----------------
extern "C" void kernel_launch(void* const* d_in, const int* in_sizes, int n_in,
                              void* d_out, int out_size) {
    (void)in_sizes; (void)n_in; (void)out_size;
    const float* x   = (const float*)d_in[0];
    const void*  pa1 = d_in[1];
    // d_in[2] = idx_re_1 (unused: re is the inverse of pa, folded into scatter)
    const void*  pa2 = d_in[3];
    // d_in[4] = idx_re_2 (unused)
    const float* cw  = (const float*)d_in[5];
    const float* gam = (const float*)d_in[6];
    const float* bet = (const float*)d_in[7];
    const float* mn  = (const float*)d_in[8];
    const float* vr  = (const float*)d_in[9];
    float* out = (float*)d_out;

    float* mid = nullptr;
    cudaGetSymbolAddress((void**)&mid, g_mid);

    static int attr_done = 0;
    if (!attr_done) {
        cudaFuncSetAttribute(block_kernel, cudaFuncAttributeMaxDynamicSharedMemorySize,
                             SMEM_BYTES);
        attr_done = 1;
    }

    const int NPREP = NBLK * 3 * 3 * 64 * 64;
    prep_kernel<<<(NPREP + 255) / 256, 256>>>(cw, gam, bet, mn, vr);

    dim3 grid(NTILE, BATCH);
    block_kernel<<<grid, NTHR, SMEM_BYTES>>>(x,   mid, pa1, 0);
    block_kernel<<<grid, NTHR, SMEM_BYTES>>>(mid, out, pa2, 1);
}

// round 8
// speedup vs baseline: 5.4095x; 1.6298x over previous
#include <cuda_runtime.h>
#include <cuda_fp16.h>
#include <cstdint>

// ---------------- problem constants ----------------
#define BATCH   2
#define NPTS    262144
#define NBLK    2
#define EPS     1e-5f

#define TJ      124                       // valid output rows per tile (M=128 computed)
#define NTILE   ((NPTS + TJ - 1) / TJ)    // 2115
#define NTHR    512
#define ROWS_X  130                       // gathered rows: j0-3 .. j0+126

// ---------------- smem byte offsets ----------------
#define SM_PA    0                        // 130 ints
#define SM_BIAS  640                      // 192 floats
#define SM_AX    1536                     // x tile,  132 rows * 128B (fp16, swizzled)
#define SM_H0    18432                    // h0 tile, 132 rows * 128B
#define SM_H1    35328                    // h1 tile, 132 rows * 128B
#define SM_W0    52224                    // weight buffer 0: 3 taps * 8192B
#define SM_W1    76800                    // weight buffer 1
#define SMEM_BYTES 101376                 // 99 KB -> 2 CTAs/SM

// ---------------- global scratch (no cudaMalloc) ----------------
__device__ float g_mid[(size_t)BATCH * NPTS * 64];
__device__ unsigned char g_wb[NBLK * 3 * 3 * 8192];   // fp16 weight images [b3l][tap], swizzled
__device__ float g_bias[NBLK * 3 * 64];

// ---------------- helpers ----------------
__device__ __forceinline__ unsigned smem_u32(const void* p) {
    unsigned a;
    asm("{ .reg .u64 t; cvta.to.shared.u64 t, %1; cvt.u32.u64 %0, t; }" : "=r"(a) : "l"(p));
    return a;
}
__device__ __forceinline__ void ldsm4(unsigned* r, unsigned addr) {
    asm volatile("ldmatrix.sync.aligned.m8n8.x4.shared.b16 {%0,%1,%2,%3}, [%4];"
                 : "=r"(r[0]), "=r"(r[1]), "=r"(r[2]), "=r"(r[3]) : "r"(addr));
}
__device__ __forceinline__ void mma_fp16(float* c, const unsigned* a, const unsigned* b) {
    asm volatile("mma.sync.aligned.m16n8k16.row.col.f32.f16.f16.f32 "
                 "{%0,%1,%2,%3}, {%4,%5,%6,%7}, {%8,%9}, {%0,%1,%2,%3};"
                 : "+f"(c[0]), "+f"(c[1]), "+f"(c[2]), "+f"(c[3])
                 : "r"(a[0]), "r"(a[1]), "r"(a[2]), "r"(a[3]), "r"(b[0]), "r"(b[1]));
}
__device__ __forceinline__ unsigned pack_h2(float v0, float v1) {   // v0 -> low half
    half2 h = __floats2half2_rn(v0, v1);
    return *(unsigned*)&h;
}
__device__ __forceinline__ void sts32(unsigned addr, unsigned v) {
    asm volatile("st.shared.b32 [%0], %1;" :: "r"(addr), "r"(v) : "memory");
}
__device__ __forceinline__ unsigned lds32(unsigned addr) {
    unsigned v;
    asm volatile("ld.shared.b32 %0, [%1];" : "=r"(v) : "r"(addr));
    return v;
}
__device__ __forceinline__ void sts_zero16(unsigned addr) {
    asm volatile("st.shared.v4.b32 [%0], {%1,%1,%1,%1};" :: "r"(addr), "r"(0u) : "memory");
}
// async 24KB weight image copy (1536 x 16B) + commit one group
__device__ __forceinline__ void weights_async(unsigned dst, const unsigned char* src, int tid) {
    for (int e = tid; e < 1536; e += NTHR)
        asm volatile("cp.async.cg.shared.global [%0], [%1], 16;"
                     :: "r"(dst + e * 16), "l"(src + (size_t)e * 16) : "memory");
    asm volatile("cp.async.commit_group;" ::: "memory");
}
#define CP_WAIT(n) asm volatile("cp.async.wait_group %0;" :: "n"(n) : "memory")

// ---------------- prep: fold BN, fp16 weights, pre-swizzle ----------------
// conv_w src: [blk][l][O][I][K]; image per (b3l, tap): [o row][i col] fp16,
// 128B rows, chunk-swizzle: chunk16 ^= (o & 7).
__global__ void prep_kernel(const float* __restrict__ cw, const float* __restrict__ gam,
                            const float* __restrict__ bet, const float* __restrict__ mn,
                            const float* __restrict__ vr) {
    int t = blockIdx.x * blockDim.x + threadIdx.x;
    const int NW = NBLK * 3 * 3 * 64 * 64;
    if (t < NW) {
        int i   = t & 63;
        int o   = (t >> 6) & 63;
        int tap = (t >> 12) % 3;
        int b3l = t / 12288;
        int ch  = b3l * 64 + o;
        float sc = gam[ch] * rsqrtf(vr[ch] + EPS);
        float v  = cw[(((size_t)b3l * 64 + o) * 64 + i) * 3 + tap] * sc;
        unsigned off = (unsigned)(o * 128 + (((i >> 3) ^ (o & 7)) << 4) + ((i & 7) << 1));
        size_t ib = (size_t)(b3l * 3 + tap) * 8192;
        *(unsigned short*)(g_wb + ib + off) = __half_as_ushort(__float2half_rn(v));
    }
    if (t < NBLK * 3 * 64) {
        float sc = gam[t] * rsqrtf(vr[t] + EPS);
        g_bias[t] = bet[t] - mn[t] * sc;
    }
}

// ---------------- fused block kernel ----------------
__global__ void __launch_bounds__(NTHR, 2)
block_kernel(const float* __restrict__ xin, float* __restrict__ xout,
             const void* __restrict__ idxp, int blk) {
    extern __shared__ char smem[];
    const unsigned sbase = smem_u32(smem);
    const int tid = threadIdx.x;
    const int w   = tid >> 5;
    const int lid = tid & 31;
    const int bb  = blockIdx.y;
    const int j0  = blockIdx.x * TJ;

    int*   s_pa   = (int*)(smem + SM_PA);
    float* s_bias = (float*)(smem + SM_BIAS);

    // index dtype detect (JAX x64 off => int32 despite astype(int64))
    const unsigned* iw = (const unsigned*)idxp;
    const bool is64 = ((iw[1] | iw[3] | iw[5] | iw[7]) == 0u);

    if (tid < ROWS_X) {                          // pa rows j0-3 .. j0+126
        int j = j0 - 3 + tid;
        int v = 0;
        if (j >= 0 && j < NPTS)
            v = is64 ? (int)((const long long*)idxp)[(size_t)bb * NPTS + j]
                     : ((const int*)idxp)[(size_t)bb * NPTS + j];
        s_pa[tid] = v;
    }
    if (tid < 192) s_bias[tid] = g_bias[blk * 192 + tid];

    // async weight staging: G0 = layer0 -> W0, G1 = layer1 -> W1 (overlaps gather)
    weights_async(sbase + SM_W0, g_wb + (size_t)(blk * 3 + 0) * 24576, tid);
    weights_async(sbase + SM_W1, g_wb + (size_t)(blk * 3 + 1) * 24576, tid);
    __syncthreads();                             // s_pa visible for gather

    // gather x through the permutation -> fp16 AX tile (zero outside sequence)
    {
        const float4* x4 = (const float4*)xin;
        for (int e = tid; e < ROWS_X * 16; e += NTHR) {
            int r = e >> 4, c4 = e & 15;
            int j = j0 - 3 + r;
            float4 v = make_float4(0.f, 0.f, 0.f, 0.f);
            if (j >= 0 && j < NPTS)
                v = x4[((size_t)bb * NPTS + (size_t)s_pa[r]) * 16 + c4];
            unsigned off = (unsigned)(r * 128 + ((((unsigned)c4 >> 1) ^ (r & 7)) << 4) + ((c4 & 1) << 3));
            *(uint2*)(smem + SM_AX + off) = make_uint2(pack_h2(v.x, v.y), pack_h2(v.z, v.w));
        }
        if (tid < 64) {   // zero rows 128..131 of H0 and H1 (read-only tails)
            int buf = tid >> 5, rr = 128 + ((tid >> 3) & 3), ch = tid & 7;
            unsigned off = (unsigned)(rr * 128 + ch * 16);
            sts_zero16(sbase + (buf ? SM_H1 : SM_H0) + off);
        }
    }
    CP_WAIT(1);                                  // G0 (layer0 weights) landed
    __syncthreads();

    // 16 warps: 4 m-groups x 4 n-groups; warp tile 32 rows x 16 cols
    const int wm  = (w & 3) * 32;
    const int wn  = (w >> 2) * 16;
    const int grp = lid >> 2;          // fragment row group
    const int qd  = lid & 3;           // fragment col quad
    const int lrow = ((lid >> 3) & 1) * 8 + (lid & 7);   // ldsm row within 16-block
    const int lch  = lid >> 4;                           // ldsm chunk select (0/1)

    for (int l = 0; l < 3; l++) {
        const unsigned inB  = sbase + (l == 0 ? SM_AX : (l == 1 ? SM_H0 : SM_H1));
        const unsigned outB = sbase + (l == 0 ? SM_H0 : SM_H1);
        const unsigned sW   = sbase + ((l == 1) ? SM_W1 : SM_W0);

        if (l == 1)   // G2 = layer2 -> W0 (W0 free), overlaps layer1 MMA
            weights_async(sbase + SM_W0, g_wb + (size_t)(blk * 3 + 2) * 24576, tid);

        float c[2][2][4];              // [mt][nt][frag]
#pragma unroll
        for (int nt = 0; nt < 2; nt++) {
            int cb = wn + nt * 8 + 2 * qd;
            float b0 = s_bias[l * 64 + cb], b1 = s_bias[l * 64 + cb + 1];
#pragma unroll
            for (int mt = 0; mt < 2; mt++) {
                c[mt][nt][0] = b0; c[mt][nt][1] = b1;
                c[mt][nt][2] = b0; c[mt][nt][3] = b1;
            }
        }

#pragma unroll
        for (int tap = 0; tap < 3; tap++) {
            const unsigned wt = sW + (unsigned)tap * 8192;
#pragma unroll
            for (int kc = 0; kc < 4; kc++) {
                const int CH = 2 * kc + lch;
                unsigned a[2][4];
#pragma unroll
                for (int mt = 0; mt < 2; mt++) {
                    int R  = wm + mt * 16 + tap + lrow;
                    unsigned off = (unsigned)(R * 128 + ((CH ^ (R & 7)) << 4));
                    ldsm4(a[mt], inB + off);
                }
                unsigned b[2][2];
                {
                    int O  = wn + lrow;
                    unsigned off = (unsigned)(O * 128 + ((CH ^ (O & 7)) << 4));
                    unsigned r4[4];
                    ldsm4(r4, wt + off);
                    b[0][0] = r4[0]; b[0][1] = r4[2];
                    b[1][0] = r4[1]; b[1][1] = r4[3];
                }
#pragma unroll
                for (int mt = 0; mt < 2; mt++)
#pragma unroll
                    for (int nt = 0; nt < 2; nt++)
                        mma_fp16(c[mt][nt], a[mt], b[nt]);
            }
        }

        if (l < 2) {
            // ---- mid epilogue: relu + boundary zero, fp16 -> out buffer ----
#pragma unroll
            for (int mt = 0; mt < 2; mt++)
#pragma unroll
                for (int h = 0; h < 2; h++) {
                    int row = wm + mt * 16 + h * 8 + grp;
                    int pos = j0 - 2 + l + row;
                    bool valid = (unsigned)pos < (unsigned)NPTS;
#pragma unroll
                    for (int nt = 0; nt < 2; nt++) {
                        float v0 = c[mt][nt][h * 2];
                        float v1 = c[mt][nt][h * 2 + 1];
                        v0 = valid ? fmaxf(v0, 0.f) : 0.f;
                        v1 = valid ? fmaxf(v1, 0.f) : 0.f;
                        int cb = wn + nt * 8 + 2 * qd;
                        unsigned off = (unsigned)(row * 128 + (((cb >> 3) ^ (row & 7)) << 4) + ((cb & 7) << 1));
                        sts32(outB + off, pack_h2(v0, v1));
                    }
                }
            CP_WAIT(0);       // next layer's weights landed
            __syncthreads();
        } else {
            // ---- final epilogue: + residual(fp16 x from AX) + relu, scatter ----
#pragma unroll
            for (int mt = 0; mt < 2; mt++)
#pragma unroll
                for (int h = 0; h < 2; h++) {
                    int row = wm + mt * 16 + h * 8 + grp;
                    if (row >= TJ) continue;
                    int pos = j0 + row;
                    if (pos >= NPTS) continue;
                    size_t obase = ((size_t)bb * NPTS + (size_t)s_pa[row + 3]) * 64;
                    int xr = row + 3;   // AX row holding x[j0+row]
#pragma unroll
                    for (int nt = 0; nt < 2; nt++) {
                        int cb = wn + nt * 8 + 2 * qd;
                        unsigned xoff = (unsigned)(xr * 128 + (((cb >> 3) ^ (xr & 7)) << 4) + ((cb & 7) << 1));
                        unsigned xb = lds32(sbase + SM_AX + xoff);
                        float2 xv = __half22float2(*(half2*)&xb);
                        float v0 = fmaxf(c[mt][nt][h * 2]     + xv.x, 0.f);
                        float v1 = fmaxf(c[mt][nt][h * 2 + 1] + xv.y, 0.f);
                        *(float2*)(xout + obase + cb) = make_float2(v0, v1);
                    }
                }
        }
    }
}

// ---------------- launch ----------------
extern "C" void kernel_launch(void* const* d_in, const int* in_sizes, int n_in,
                              void* d_out, int out_size) {
    (void)in_sizes; (void)n_in; (void)out_size;
    const float* x   = (const float*)d_in[0];
    const void*  pa1 = d_in[1];
    // d_in[2] = idx_re_1 (unused: re is the inverse of pa, folded into scatter)
    const void*  pa2 = d_in[3];
    // d_in[4] = idx_re_2 (unused)
    const float* cw  = (const float*)d_in[5];
    const float* gam = (const float*)d_in[6];
    const float* bet = (const float*)d_in[7];
    const float* mn  = (const float*)d_in[8];
    const float* vr  = (const float*)d_in[9];
    float* out = (float*)d_out;

    float* mid = nullptr;
    cudaGetSymbolAddress((void**)&mid, g_mid);

    static int attr_done = 0;
    if (!attr_done) {
        cudaFuncSetAttribute(block_kernel, cudaFuncAttributeMaxDynamicSharedMemorySize,
                             SMEM_BYTES);
        attr_done = 1;
    }

    const int NPREP = NBLK * 3 * 3 * 64 * 64;
    prep_kernel<<<(NPREP + 255) / 256, 256>>>(cw, gam, bet, mn, vr);

    dim3 grid(NTILE, BATCH);
    block_kernel<<<grid, NTHR, SMEM_BYTES>>>(x,   mid, pa1, 0);
    block_kernel<<<grid, NTHR, SMEM_BYTES>>>(mid, out, pa2, 1);
}

// round 10
// speedup vs baseline: 8.6098x; 1.5916x over previous
#include <cuda_runtime.h>
#include <cuda_fp16.h>
#include <cstdint>

// ---------------- problem constants ----------------
#define BATCH   2
#define NPTS    262144
#define NBLK    2
#define EPS     1e-5f

#define TJ      124                       // valid output rows per tile (M=128 computed)
#define NTILE   ((NPTS + TJ - 1) / TJ)    // 2115
#define NTHR    512
#define ROWS_X  130                       // gathered rows: j0-3 .. j0+126

// ---------------- smem byte offsets ----------------
#define SM_PA    0                        // 130 ints
#define SM_BIAS  640                      // 192 floats
#define SM_AX    1536                     // x tile,  132 rows * 128B (fp16, swizzled)
#define SM_H0    18432                    // h0 tile, 132 rows * 128B
#define SM_H1    35328                    // h1 tile, 132 rows * 128B
#define SM_W0    52224                    // weight buffer 0: 3 taps * 8192B
#define SM_W1    76800                    // weight buffer 1
#define SMEM_BYTES 101376                 // 99 KB -> 2 CTAs/SM

// ---------------- global scratch (no cudaMalloc) ----------------
__device__ float g_mid[(size_t)BATCH * NPTS * 64];
__device__ unsigned char g_wb[NBLK * 3 * 3 * 8192];   // fp16 weight images [b3l][tap], swizzled
__device__ float g_bias[NBLK * 3 * 64];

// ---------------- helpers ----------------
__device__ __forceinline__ unsigned smem_u32(const void* p) {
    unsigned a;
    asm("{ .reg .u64 t; cvta.to.shared.u64 t, %1; cvt.u32.u64 %0, t; }" : "=r"(a) : "l"(p));
    return a;
}
__device__ __forceinline__ void ldsm4(unsigned* r, unsigned addr) {
    asm volatile("ldmatrix.sync.aligned.m8n8.x4.shared.b16 {%0,%1,%2,%3}, [%4];"
                 : "=r"(r[0]), "=r"(r[1]), "=r"(r[2]), "=r"(r[3]) : "r"(addr));
}
__device__ __forceinline__ void mma_fp16(float* c, const unsigned* a, const unsigned* b) {
    asm volatile("mma.sync.aligned.m16n8k16.row.col.f32.f16.f16.f32 "
                 "{%0,%1,%2,%3}, {%4,%5,%6,%7}, {%8,%9}, {%0,%1,%2,%3};"
                 : "+f"(c[0]), "+f"(c[1]), "+f"(c[2]), "+f"(c[3])
                 : "r"(a[0]), "r"(a[1]), "r"(a[2]), "r"(a[3]), "r"(b[0]), "r"(b[1]));
}
__device__ __forceinline__ unsigned pack_h2(float v0, float v1) {   // v0 -> low half
    half2 h = __floats2half2_rn(v0, v1);
    return *(unsigned*)&h;
}
__device__ __forceinline__ void sts32(unsigned addr, unsigned v) {
    asm volatile("st.shared.b32 [%0], %1;" :: "r"(addr), "r"(v) : "memory");
}
__device__ __forceinline__ unsigned lds32(unsigned addr) {
    unsigned v;
    asm volatile("ld.shared.b32 %0, [%1];" : "=r"(v) : "r"(addr));
    return v;
}
__device__ __forceinline__ void sts_zero16(unsigned addr) {
    asm volatile("st.shared.v4.b32 [%0], {%1,%1,%1,%1};" :: "r"(addr), "r"(0u) : "memory");
}
// async 24KB weight image copy (1536 x 16B) + commit one group
__device__ __forceinline__ void weights_async(unsigned dst, const unsigned char* src, int tid) {
    for (int e = tid; e < 1536; e += NTHR)
        asm volatile("cp.async.cg.shared.global [%0], [%1], 16;"
                     :: "r"(dst + e * 16), "l"(src + (size_t)e * 16) : "memory");
    asm volatile("cp.async.commit_group;" ::: "memory");
}
#define CP_WAIT(n) asm volatile("cp.async.wait_group %0;" :: "n"(n) : "memory")

// ---------------- prep: fold BN, fp16 weights, pre-swizzle ----------------
// conv_w src: [blk][l][O][I][K]; image per (b3l, tap): [o row][i col] fp16,
// 128B rows, chunk-swizzle: chunk16 ^= (o & 7).
__global__ void prep_kernel(const float* __restrict__ cw, const float* __restrict__ gam,
                            const float* __restrict__ bet, const float* __restrict__ mn,
                            const float* __restrict__ vr) {
    int t = blockIdx.x * blockDim.x + threadIdx.x;
    const int NW = NBLK * 3 * 3 * 64 * 64;
    if (t < NW) {
        int i   = t & 63;
        int o   = (t >> 6) & 63;
        int tap = (t >> 12) % 3;
        int b3l = t / 12288;
        int ch  = b3l * 64 + o;
        float sc = gam[ch] * rsqrtf(vr[ch] + EPS);
        float v  = cw[(((size_t)b3l * 64 + o) * 64 + i) * 3 + tap] * sc;
        unsigned off = (unsigned)(o * 128 + (((i >> 3) ^ (o & 7)) << 4) + ((i & 7) << 1));
        size_t ib = (size_t)(b3l * 3 + tap) * 8192;
        *(unsigned short*)(g_wb + ib + off) = __half_as_ushort(__float2half_rn(v));
    }
    if (t < NBLK * 3 * 64) {
        float sc = gam[t] * rsqrtf(vr[t] + EPS);
        g_bias[t] = bet[t] - mn[t] * sc;
    }
}

// ---------------- fused block kernel (one batch element per launch) ----------------
__global__ void __launch_bounds__(NTHR, 2)
block_kernel(const float* __restrict__ xin, float* __restrict__ xout,
             const void* __restrict__ idxp, int blk, int bb) {
    extern __shared__ char smem[];
    const unsigned sbase = smem_u32(smem);
    const int tid = threadIdx.x;
    const int w   = tid >> 5;
    const int lid = tid & 31;
    const int j0  = blockIdx.x * TJ;

    int*   s_pa   = (int*)(smem + SM_PA);
    float* s_bias = (float*)(smem + SM_BIAS);

    // index dtype detect (JAX x64 off => int32 despite astype(int64))
    const unsigned* iw = (const unsigned*)idxp;
    const bool is64 = ((iw[1] | iw[3] | iw[5] | iw[7]) == 0u);
    const long long* p64 = (const long long*)idxp;
    const int*       p32 = (const int*)idxp;

    if (tid < ROWS_X) {                          // pa rows j0-3 .. j0+126 (for scatter)
        int j = j0 - 3 + tid;
        int v = 0;
        if (j >= 0 && j < NPTS)
            v = is64 ? (int)p64[(size_t)bb * NPTS + j] : p32[(size_t)bb * NPTS + j];
        s_pa[tid] = v;
    }
    if (tid < 192) s_bias[tid] = g_bias[blk * 192 + tid];

    // async weight staging: G0 = layer0 -> W0, G1 = layer1 -> W1 (overlaps gather)
    weights_async(sbase + SM_W0, g_wb + (size_t)(blk * 3 + 0) * 24576, tid);
    weights_async(sbase + SM_W1, g_wb + (size_t)(blk * 3 + 1) * 24576, tid);

    // gather x through the permutation -> fp16 AX tile (zero outside sequence).
    // pa read directly from global (no sync needed); fully unrolled for MLP=5.
    {
        const float4* x4 = (const float4*)xin;
        float4 v[5];
        int    jv[5];
#pragma unroll
        for (int u = 0; u < 5; u++) {
            int e  = tid + u * NTHR;
            bool on = (u < 4) || (tid < ROWS_X * 16 - 4 * NTHR);
            int r  = e >> 4;
            int j  = j0 - 3 + r;
            bool valid = on && (j >= 0) && (j < NPTS);
            int pa = 0;
            if (valid) pa = is64 ? (int)p64[(size_t)bb * NPTS + j] : p32[(size_t)bb * NPTS + j];
            v[u] = make_float4(0.f, 0.f, 0.f, 0.f);
            if (valid) v[u] = x4[((size_t)bb * NPTS + (size_t)pa) * 16 + (e & 15)];
            jv[u] = on;
        }
#pragma unroll
        for (int u = 0; u < 5; u++) {
            if (!jv[u]) continue;
            int e = tid + u * NTHR;
            int r = e >> 4, c4 = e & 15;
            unsigned off = (unsigned)(r * 128 + ((((unsigned)c4 >> 1) ^ (r & 7)) << 4) + ((c4 & 1) << 3));
            *(uint2*)(smem + SM_AX + off) = make_uint2(pack_h2(v[u].x, v[u].y), pack_h2(v[u].z, v[u].w));
        }
        if (tid < 64) {   // zero rows 128..131 of H0 and H1 (read-only tails)
            int buf = tid >> 5, rr = 128 + ((tid >> 3) & 3), ch = tid & 7;
            unsigned off = (unsigned)(rr * 128 + ch * 16);
            sts_zero16(sbase + (buf ? SM_H1 : SM_H0) + off);
        }
    }
    CP_WAIT(1);                                  // G0 (layer0 weights) landed
    __syncthreads();                             // AX, s_pa, bias, W0 all visible

    // 16 warps: 4 m-groups x 4 n-groups; warp tile 32 rows x 16 cols
    const int wm  = (w & 3) * 32;
    const int wn  = (w >> 2) * 16;
    const int grp = lid >> 2;          // fragment row group
    const int qd  = lid & 3;           // fragment col quad
    const int lrow = ((lid >> 3) & 1) * 8 + (lid & 7);   // ldsm row within 16-block
    const int lch  = lid >> 4;                           // ldsm chunk select (0/1)

    for (int l = 0; l < 3; l++) {
        const unsigned inB  = sbase + (l == 0 ? SM_AX : (l == 1 ? SM_H0 : SM_H1));
        const unsigned outB = sbase + (l == 0 ? SM_H0 : SM_H1);
        const unsigned sW   = sbase + ((l == 1) ? SM_W1 : SM_W0);

        if (l == 1)   // G2 = layer2 -> W0 (W0 free), overlaps layer1 MMA
            weights_async(sbase + SM_W0, g_wb + (size_t)(blk * 3 + 2) * 24576, tid);

        float c[2][2][4];              // [mt][nt][frag]
#pragma unroll
        for (int nt = 0; nt < 2; nt++) {
            int cb = wn + nt * 8 + 2 * qd;
            float b0 = s_bias[l * 64 + cb], b1 = s_bias[l * 64 + cb + 1];
#pragma unroll
            for (int mt = 0; mt < 2; mt++) {
                c[mt][nt][0] = b0; c[mt][nt][1] = b1;
                c[mt][nt][2] = b0; c[mt][nt][3] = b1;
            }
        }

#pragma unroll
        for (int tap = 0; tap < 3; tap++) {
            const unsigned wt = sW + (unsigned)tap * 8192;
#pragma unroll
            for (int kc = 0; kc < 4; kc++) {
                const int CH = 2 * kc + lch;
                unsigned a[2][4];
#pragma unroll
                for (int mt = 0; mt < 2; mt++) {
                    int R  = wm + mt * 16 + tap + lrow;
                    unsigned off = (unsigned)(R * 128 + ((CH ^ (R & 7)) << 4));
                    ldsm4(a[mt], inB + off);
                }
                unsigned b[2][2];
                {
                    int O  = wn + lrow;
                    unsigned off = (unsigned)(O * 128 + ((CH ^ (O & 7)) << 4));
                    unsigned r4[4];
                    ldsm4(r4, wt + off);
                    b[0][0] = r4[0]; b[0][1] = r4[2];
                    b[1][0] = r4[1]; b[1][1] = r4[3];
                }
#pragma unroll
                for (int mt = 0; mt < 2; mt++)
#pragma unroll
                    for (int nt = 0; nt < 2; nt++)
                        mma_fp16(c[mt][nt], a[mt], b[nt]);
            }
        }

        if (l < 2) {
            // ---- mid epilogue: relu + boundary zero, fp16 -> out buffer ----
#pragma unroll
            for (int mt = 0; mt < 2; mt++)
#pragma unroll
                for (int h = 0; h < 2; h++) {
                    int row = wm + mt * 16 + h * 8 + grp;
                    int pos = j0 - 2 + l + row;
                    bool valid = (unsigned)pos < (unsigned)NPTS;
#pragma unroll
                    for (int nt = 0; nt < 2; nt++) {
                        float v0 = c[mt][nt][h * 2];
                        float v1 = c[mt][nt][h * 2 + 1];
                        v0 = valid ? fmaxf(v0, 0.f) : 0.f;
                        v1 = valid ? fmaxf(v1, 0.f) : 0.f;
                        int cb = wn + nt * 8 + 2 * qd;
                        unsigned off = (unsigned)(row * 128 + (((cb >> 3) ^ (row & 7)) << 4) + ((cb & 7) << 1));
                        sts32(outB + off, pack_h2(v0, v1));
                    }
                }
            CP_WAIT(0);       // next layer's weights landed
            __syncthreads();
        } else {
            // ---- final epilogue: + residual(fp16 x from AX) + relu, scatter ----
#pragma unroll
            for (int mt = 0; mt < 2; mt++)
#pragma unroll
                for (int h = 0; h < 2; h++) {
                    int row = wm + mt * 16 + h * 8 + grp;
                    if (row >= TJ) continue;
                    int pos = j0 + row;
                    if (pos >= NPTS) continue;
                    size_t obase = ((size_t)bb * NPTS + (size_t)s_pa[row + 3]) * 64;
                    int xr = row + 3;   // AX row holding x[j0+row]
#pragma unroll
                    for (int nt = 0; nt < 2; nt++) {
                        int cb = wn + nt * 8 + 2 * qd;
                        unsigned xoff = (unsigned)(xr * 128 + (((cb >> 3) ^ (xr & 7)) << 4) + ((cb & 7) << 1));
                        unsigned xb = lds32(sbase + SM_AX + xoff);
                        float2 xv = __half22float2(*(half2*)&xb);
                        float v0 = fmaxf(c[mt][nt][h * 2]     + xv.x, 0.f);
                        float v1 = fmaxf(c[mt][nt][h * 2 + 1] + xv.y, 0.f);
                        *(float2*)(xout + obase + cb) = make_float2(v0, v1);
                    }
                }
        }
    }
}

// ---------------- launch: per-batch fork-join (overlap kernel drains) ----------------
extern "C" void kernel_launch(void* const* d_in, const int* in_sizes, int n_in,
                              void* d_out, int out_size) {
    (void)in_sizes; (void)n_in; (void)out_size;
    const float* x   = (const float*)d_in[0];
    const void*  pa1 = d_in[1];
    // d_in[2] = idx_re_1 (unused: re is the inverse of pa, folded into scatter)
    const void*  pa2 = d_in[3];
    // d_in[4] = idx_re_2 (unused)
    const float* cw  = (const float*)d_in[5];
    const float* gam = (const float*)d_in[6];
    const float* bet = (const float*)d_in[7];
    const float* mn  = (const float*)d_in[8];
    const float* vr  = (const float*)d_in[9];
    float* out = (float*)d_out;

    float* mid = nullptr;
    cudaGetSymbolAddress((void**)&mid, g_mid);

    static cudaStream_t s1 = nullptr, s2 = nullptr;
    static cudaEvent_t  e0 = nullptr, e1 = nullptr, e2 = nullptr;
    static int attr_done = 0;
    if (!attr_done) {
        cudaFuncSetAttribute(block_kernel, cudaFuncAttributeMaxDynamicSharedMemorySize,
                             SMEM_BYTES);
        cudaStreamCreateWithFlags(&s1, cudaStreamNonBlocking);
        cudaStreamCreateWithFlags(&s2, cudaStreamNonBlocking);
        cudaEventCreateWithFlags(&e0, cudaEventDisableTiming);
        cudaEventCreateWithFlags(&e1, cudaEventDisableTiming);
        cudaEventCreateWithFlags(&e2, cudaEventDisableTiming);
        attr_done = 1;
    }

    const int NPREP = NBLK * 3 * 3 * 64 * 64;
    prep_kernel<<<(NPREP + 255) / 256, 256>>>(cw, gam, bet, mn, vr);

    // fork: two independent per-batch chains
    cudaEventRecord(e0, 0);
    cudaStreamWaitEvent(s1, e0, 0);
    cudaStreamWaitEvent(s2, e0, 0);

    dim3 grid(NTILE, 1);
    block_kernel<<<grid, NTHR, SMEM_BYTES, s1>>>(x,   mid, pa1, 0, 0);
    block_kernel<<<grid, NTHR, SMEM_BYTES, s1>>>(mid, out, pa2, 1, 0);
    block_kernel<<<grid, NTHR, SMEM_BYTES, s2>>>(x,   mid, pa1, 0, 1);
    block_kernel<<<grid, NTHR, SMEM_BYTES, s2>>>(mid, out, pa2, 1, 1);

    // join back to the captured origin stream
    cudaEventRecord(e1, s1);
    cudaEventRecord(e2, s2);
    cudaStreamWaitEvent(0, e1, 0);
    cudaStreamWaitEvent(0, e2, 0);
}

// round 11
// speedup vs baseline: 10.4999x; 1.2195x over previous
#include <cuda_runtime.h>
#include <cuda_fp16.h>
#include <cstdint>

// ---------------- problem constants ----------------
#define BATCH   2
#define NPTS    262144
#define NBLK    2
#define EPS     1e-5f

#define TJ      124                       // valid output rows per tile (M=128 computed)
#define NTILE   ((NPTS + TJ - 1) / TJ)    // 2115
#define NTHR    256
#define ROWS_X  130                       // gathered rows: j0-3 .. j0+126

// ---------------- smem byte offsets (130-row tiles, single W buffer) ----------------
#define SM_PA    0                        // 130 ints (pad to 640)
#define SM_AX    640                      // x tile,  130 rows * 128B (fp16, swizzled)
#define SM_H0    17280                    // h0 tile, 130 rows * 128B
#define SM_H1    33920                    // h1 tile, 130 rows * 128B
#define SM_W     50560                    // weight buffer: 3 taps * 8192B
#define SMEM_BYTES 75136                  // 73.4 KB -> 3 CTAs/SM

// ---------------- global scratch (no cudaMalloc) ----------------
__device__ float g_mid[(size_t)BATCH * NPTS * 64];
__device__ unsigned char g_wb[NBLK * 3 * 3 * 8192];   // fp16 weight images [b3l][tap], swizzled
__device__ float g_bias[NBLK * 3 * 64];

// ---------------- helpers ----------------
__device__ __forceinline__ unsigned smem_u32(const void* p) {
    unsigned a;
    asm("{ .reg .u64 t; cvta.to.shared.u64 t, %1; cvt.u32.u64 %0, t; }" : "=r"(a) : "l"(p));
    return a;
}
__device__ __forceinline__ void ldsm4(unsigned* r, unsigned addr) {
    asm volatile("ldmatrix.sync.aligned.m8n8.x4.shared.b16 {%0,%1,%2,%3}, [%4];"
                 : "=r"(r[0]), "=r"(r[1]), "=r"(r[2]), "=r"(r[3]) : "r"(addr));
}
__device__ __forceinline__ void mma_fp16(float* c, const unsigned* a, const unsigned* b) {
    asm volatile("mma.sync.aligned.m16n8k16.row.col.f32.f16.f16.f32 "
                 "{%0,%1,%2,%3}, {%4,%5,%6,%7}, {%8,%9}, {%0,%1,%2,%3};"
                 : "+f"(c[0]), "+f"(c[1]), "+f"(c[2]), "+f"(c[3])
                 : "r"(a[0]), "r"(a[1]), "r"(a[2]), "r"(a[3]), "r"(b[0]), "r"(b[1]));
}
__device__ __forceinline__ unsigned pack_h2(float v0, float v1) {   // v0 -> low half
    half2 h = __floats2half2_rn(v0, v1);
    return *(unsigned*)&h;
}
__device__ __forceinline__ void sts32(unsigned addr, unsigned v) {
    asm volatile("st.shared.b32 [%0], %1;" :: "r"(addr), "r"(v) : "memory");
}
__device__ __forceinline__ unsigned lds32(unsigned addr) {
    unsigned v;
    asm volatile("ld.shared.b32 %0, [%1];" : "=r"(v) : "r"(addr));
    return v;
}
__device__ __forceinline__ void sts_zero16(unsigned addr) {
    asm volatile("st.shared.v4.b32 [%0], {%1,%1,%1,%1};" :: "r"(addr), "r"(0u) : "memory");
}
// async 24KB weight image copy (1536 x 16B) + commit one group
__device__ __forceinline__ void weights_async(unsigned dst, const unsigned char* src, int tid) {
    for (int e = tid; e < 1536; e += NTHR)
        asm volatile("cp.async.cg.shared.global [%0], [%1], 16;"
                     :: "r"(dst + e * 16), "l"(src + (size_t)e * 16) : "memory");
    asm volatile("cp.async.commit_group;" ::: "memory");
}
#define CP_WAIT(n) asm volatile("cp.async.wait_group %0;" :: "n"(n) : "memory")

// ---------------- prep: fold BN, fp16 weights, pre-swizzle ----------------
// conv_w src: [blk][l][O][I][K]; image per (b3l, tap): [o row][i col] fp16,
// 128B rows, chunk-swizzle: chunk16 ^= (o & 7).
__global__ void prep_kernel(const float* __restrict__ cw, const float* __restrict__ gam,
                            const float* __restrict__ bet, const float* __restrict__ mn,
                            const float* __restrict__ vr) {
    int t = blockIdx.x * blockDim.x + threadIdx.x;
    const int NW = NBLK * 3 * 3 * 64 * 64;
    if (t < NW) {
        int i   = t & 63;
        int o   = (t >> 6) & 63;
        int tap = (t >> 12) % 3;
        int b3l = t / 12288;
        int ch  = b3l * 64 + o;
        float sc = gam[ch] * rsqrtf(vr[ch] + EPS);
        float v  = cw[(((size_t)b3l * 64 + o) * 64 + i) * 3 + tap] * sc;
        unsigned off = (unsigned)(o * 128 + (((i >> 3) ^ (o & 7)) << 4) + ((i & 7) << 1));
        size_t ib = (size_t)(b3l * 3 + tap) * 8192;
        *(unsigned short*)(g_wb + ib + off) = __half_as_ushort(__float2half_rn(v));
    }
    if (t < NBLK * 3 * 64) {
        float sc = gam[t] * rsqrtf(vr[t] + EPS);
        g_bias[t] = bet[t] - mn[t] * sc;
    }
}

// ---------------- fused block kernel (one batch element per launch) ----------------
__global__ void __launch_bounds__(NTHR, 3)
block_kernel(const float* __restrict__ xin, float* __restrict__ xout,
             const void* __restrict__ idxp, int blk, int bb) {
    extern __shared__ char smem[];
    const unsigned sbase = smem_u32(smem);
    const int tid = threadIdx.x;
    const int w   = tid >> 5;
    const int lid = tid & 31;
    const int j0  = blockIdx.x * TJ;

    int* s_pa = (int*)(smem + SM_PA);

    // index dtype detect (JAX x64 off => int32 despite astype(int64))
    const unsigned* iw = (const unsigned*)idxp;
    const bool is64 = ((iw[1] | iw[3] | iw[5] | iw[7]) == 0u);
    const long long* p64 = (const long long*)idxp;
    const int*       p32 = (const int*)idxp;

    if (tid < ROWS_X) {                          // pa rows j0-3 .. j0+126 (for scatter)
        int j = j0 - 3 + tid;
        int v = 0;
        if (j >= 0 && j < NPTS)
            v = is64 ? (int)p64[(size_t)bb * NPTS + j] : p32[(size_t)bb * NPTS + j];
        s_pa[tid] = v;
    }

    // async weight staging for layer 0 (overlaps gather)
    weights_async(sbase + SM_W, g_wb + (size_t)(blk * 3 + 0) * 24576, tid);

    // gather x through the permutation -> fp16 AX tile (zero outside sequence).
    // pa read directly from global; fully unrolled for high MLP.
    {
        const float4* x4 = (const float4*)xin;
        float4 v[9];
        int    jv[9];
#pragma unroll
        for (int u = 0; u < 9; u++) {
            int e  = tid + u * NTHR;
            bool on = (u < 8) || (tid < ROWS_X * 16 - 8 * NTHR);
            int r  = e >> 4;
            int j  = j0 - 3 + r;
            bool valid = on && (j >= 0) && (j < NPTS);
            int pa = 0;
            if (valid) pa = is64 ? (int)p64[(size_t)bb * NPTS + j] : p32[(size_t)bb * NPTS + j];
            v[u] = make_float4(0.f, 0.f, 0.f, 0.f);
            if (valid) v[u] = x4[((size_t)bb * NPTS + (size_t)pa) * 16 + (e & 15)];
            jv[u] = on;
        }
#pragma unroll
        for (int u = 0; u < 9; u++) {
            if (!jv[u]) continue;
            int e = tid + u * NTHR;
            int r = e >> 4, c4 = e & 15;
            unsigned off = (unsigned)(r * 128 + ((((unsigned)c4 >> 1) ^ (r & 7)) << 4) + ((c4 & 1) << 3));
            *(uint2*)(smem + SM_AX + off) = make_uint2(pack_h2(v[u].x, v[u].y), pack_h2(v[u].z, v[u].w));
        }
        if (tid < 32) {   // zero rows 128,129 of H0 and H1 (read-only tails)
            int buf = (tid >> 4) & 1, rr = 128 + ((tid >> 3) & 1), ch = tid & 7;
            unsigned off = (unsigned)(rr * 128 + ch * 16);
            sts_zero16(sbase + (buf ? SM_H1 : SM_H0) + off);
        }
    }
    CP_WAIT(0);                                  // layer-0 weights landed
    __syncthreads();                             // AX, s_pa, W all visible

    // 8 warps: 4 m-groups x 2 n-groups; warp tile 32 rows x 32 cols
    const int wm  = (w & 3) * 32;
    const int wn  = (w >> 2) * 32;
    const int grp = lid >> 2;          // fragment row group
    const int qd  = lid & 3;           // fragment col quad
    const int lrow = ((lid >> 3) & 1) * 8 + (lid & 7);   // ldsm row within 16-block
    const int lch  = lid >> 4;                           // ldsm chunk select (0/1)

    const float* gb = g_bias + blk * 192;

    for (int l = 0; l < 3; l++) {
        const unsigned inB  = sbase + (l == 0 ? SM_AX : (l == 1 ? SM_H0 : SM_H1));
        const unsigned outB = sbase + (l == 0 ? SM_H0 : SM_H1);
        const unsigned sW   = sbase + SM_W;

        float c[2][4][4];              // [mt][nt][frag]
#pragma unroll
        for (int nt = 0; nt < 4; nt++) {
            int cb = wn + nt * 8 + 2 * qd;
            float2 bv = __ldg((const float2*)(gb + l * 64 + cb));
#pragma unroll
            for (int mt = 0; mt < 2; mt++) {
                c[mt][nt][0] = bv.x; c[mt][nt][1] = bv.y;
                c[mt][nt][2] = bv.x; c[mt][nt][3] = bv.y;
            }
        }

#pragma unroll
        for (int tap = 0; tap < 3; tap++) {
            const unsigned wt = sW + (unsigned)tap * 8192;
#pragma unroll
            for (int kc = 0; kc < 4; kc++) {
                const int CH = 2 * kc + lch;
                unsigned a[2][4];
#pragma unroll
                for (int mt = 0; mt < 2; mt++) {
                    int R  = wm + mt * 16 + tap + lrow;
                    unsigned off = (unsigned)(R * 128 + ((CH ^ (R & 7)) << 4));
                    ldsm4(a[mt], inB + off);
                }
                unsigned b[4][2];
#pragma unroll
                for (int ng = 0; ng < 2; ng++) {
                    int O  = wn + ng * 16 + lrow;
                    unsigned off = (unsigned)(O * 128 + ((CH ^ (O & 7)) << 4));
                    unsigned r4[4];
                    ldsm4(r4, wt + off);
                    b[ng * 2][0]     = r4[0]; b[ng * 2][1]     = r4[2];
                    b[ng * 2 + 1][0] = r4[1]; b[ng * 2 + 1][1] = r4[3];
                }
#pragma unroll
                for (int mt = 0; mt < 2; mt++)
#pragma unroll
                    for (int nt = 0; nt < 4; nt++)
                        mma_fp16(c[mt][nt], a[mt], b[nt]);
            }
        }

        if (l < 2) {
            __syncthreads();   // all warps done reading W(l) before overwrite
            // prefetch next layer's weights; overlaps the epilogue below
            weights_async(sbase + SM_W, g_wb + (size_t)(blk * 3 + l + 1) * 24576, tid);

            // ---- mid epilogue: relu + boundary zero, fp16 -> out buffer ----
#pragma unroll
            for (int mt = 0; mt < 2; mt++)
#pragma unroll
                for (int h = 0; h < 2; h++) {
                    int row = wm + mt * 16 + h * 8 + grp;
                    int pos = j0 - 2 + l + row;
                    bool valid = (unsigned)pos < (unsigned)NPTS;
#pragma unroll
                    for (int nt = 0; nt < 4; nt++) {
                        float v0 = c[mt][nt][h * 2];
                        float v1 = c[mt][nt][h * 2 + 1];
                        v0 = valid ? fmaxf(v0, 0.f) : 0.f;
                        v1 = valid ? fmaxf(v1, 0.f) : 0.f;
                        int cb = wn + nt * 8 + 2 * qd;
                        unsigned off = (unsigned)(row * 128 + (((cb >> 3) ^ (row & 7)) << 4) + ((cb & 7) << 1));
                        sts32(outB + off, pack_h2(v0, v1));
                    }
                }
            CP_WAIT(0);        // next layer's weights landed
            __syncthreads();   // epilogue H writes + W visible
        } else {
            // ---- final epilogue: + residual(fp16 x from AX) + relu, scatter ----
#pragma unroll
            for (int mt = 0; mt < 2; mt++)
#pragma unroll
                for (int h = 0; h < 2; h++) {
                    int row = wm + mt * 16 + h * 8 + grp;
                    if (row >= TJ) continue;
                    int pos = j0 + row;
                    if (pos >= NPTS) continue;
                    size_t obase = ((size_t)bb * NPTS + (size_t)s_pa[row + 3]) * 64;
                    int xr = row + 3;   // AX row holding x[j0+row]
#pragma unroll
                    for (int nt = 0; nt < 4; nt++) {
                        int cb = wn + nt * 8 + 2 * qd;
                        unsigned xoff = (unsigned)(xr * 128 + (((cb >> 3) ^ (xr & 7)) << 4) + ((cb & 7) << 1));
                        unsigned xb = lds32(sbase + SM_AX + xoff);
                        float2 xv = __half22float2(*(half2*)&xb);
                        float v0 = fmaxf(c[mt][nt][h * 2]     + xv.x, 0.f);
                        float v1 = fmaxf(c[mt][nt][h * 2 + 1] + xv.y, 0.f);
                        *(float2*)(xout + obase + cb) = make_float2(v0, v1);
                    }
                }
        }
    }
}

// ---------------- launch: per-batch fork-join (overlap kernel drains) ----------------
extern "C" void kernel_launch(void* const* d_in, const int* in_sizes, int n_in,
                              void* d_out, int out_size) {
    (void)in_sizes; (void)n_in; (void)out_size;
    const float* x   = (const float*)d_in[0];
    const void*  pa1 = d_in[1];
    // d_in[2] = idx_re_1 (unused: re is the inverse of pa, folded into scatter)
    const void*  pa2 = d_in[3];
    // d_in[4] = idx_re_2 (unused)
    const float* cw  = (const float*)d_in[5];
    const float* gam = (const float*)d_in[6];
    const float* bet = (const float*)d_in[7];
    const float* mn  = (const float*)d_in[8];
    const float* vr  = (const float*)d_in[9];
    float* out = (float*)d_out;

    float* mid = nullptr;
    cudaGetSymbolAddress((void**)&mid, g_mid);

    static cudaStream_t s1 = nullptr, s2 = nullptr;
    static cudaEvent_t  e0 = nullptr, e1 = nullptr, e2 = nullptr;
    static int attr_done = 0;
    if (!attr_done) {
        cudaFuncSetAttribute(block_kernel, cudaFuncAttributeMaxDynamicSharedMemorySize,
                             SMEM_BYTES);
        cudaStreamCreateWithFlags(&s1, cudaStreamNonBlocking);
        cudaStreamCreateWithFlags(&s2, cudaStreamNonBlocking);
        cudaEventCreateWithFlags(&e0, cudaEventDisableTiming);
        cudaEventCreateWithFlags(&e1, cudaEventDisableTiming);
        cudaEventCreateWithFlags(&e2, cudaEventDisableTiming);
        attr_done = 1;
    }

    const int NPREP = NBLK * 3 * 3 * 64 * 64;
    prep_kernel<<<(NPREP + 255) / 256, 256>>>(cw, gam, bet, mn, vr);

    // fork: two independent per-batch chains
    cudaEventRecord(e0, 0);
    cudaStreamWaitEvent(s1, e0, 0);
    cudaStreamWaitEvent(s2, e0, 0);

    dim3 grid(NTILE, 1);
    block_kernel<<<grid, NTHR, SMEM_BYTES, s1>>>(x,   mid, pa1, 0, 0);
    block_kernel<<<grid, NTHR, SMEM_BYTES, s1>>>(mid, out, pa2, 1, 0);
    block_kernel<<<grid, NTHR, SMEM_BYTES, s2>>>(x,   mid, pa1, 0, 1);
    block_kernel<<<grid, NTHR, SMEM_BYTES, s2>>>(mid, out, pa2, 1, 1);

    // join back to the captured origin stream
    cudaEventRecord(e1, s1);
    cudaEventRecord(e2, s2);
    cudaStreamWaitEvent(0, e1, 0);
    cudaStreamWaitEvent(0, e2, 0);
}

// round 12
// speedup vs baseline: 11.3400x; 1.0800x over previous
#include <cuda_runtime.h>
#include <cuda_fp16.h>
#include <cstdint>

// ---------------- problem constants ----------------
#define BATCH   2
#define NPTS    262144
#define NBLK    2
#define EPS     1e-5f

#define TJ      124                       // valid output rows per tile (M=128 computed)
#define NTILE   ((NPTS + TJ - 1) / TJ)    // 2115
#define NTHR    128                       // 4 warps: warp grid 2m x 2n, warp tile 64x32
#define ROWS_X  130                       // gathered rows: j0-3 .. j0+126

// ---------------- smem byte offsets (130-row tiles, single W buffer) ----------------
#define SM_PA    0                        // 130 ints (pad to 640)
#define SM_AX    640                      // x tile,  130 rows * 128B (fp16, swizzled)
#define SM_H0    17280                    // h0 tile, 130 rows * 128B
#define SM_H1    33920                    // h1 tile, 130 rows * 128B
#define SM_W     50560                    // weight buffer: 3 taps * 8192B
#define SMEM_BYTES 75136                  // 73.4 KB -> 3 CTAs/SM

// ---------------- global scratch (no cudaMalloc) ----------------
__device__ float g_mid[(size_t)BATCH * NPTS * 64];
__device__ unsigned char g_wb[NBLK * 3 * 3 * 8192];   // fp16 weight images [b3l][tap], swizzled
__device__ float g_bias[NBLK * 3 * 64];

// ---------------- helpers ----------------
__device__ __forceinline__ unsigned smem_u32(const void* p) {
    unsigned a;
    asm("{ .reg .u64 t; cvta.to.shared.u64 t, %1; cvt.u32.u64 %0, t; }" : "=r"(a) : "l"(p));
    return a;
}
__device__ __forceinline__ void ldsm4(unsigned* r, unsigned addr) {
    asm volatile("ldmatrix.sync.aligned.m8n8.x4.shared.b16 {%0,%1,%2,%3}, [%4];"
                 : "=r"(r[0]), "=r"(r[1]), "=r"(r[2]), "=r"(r[3]) : "r"(addr));
}
__device__ __forceinline__ void mma_fp16(float* c, const unsigned* a, const unsigned* b) {
    asm volatile("mma.sync.aligned.m16n8k16.row.col.f32.f16.f16.f32 "
                 "{%0,%1,%2,%3}, {%4,%5,%6,%7}, {%8,%9}, {%0,%1,%2,%3};"
                 : "+f"(c[0]), "+f"(c[1]), "+f"(c[2]), "+f"(c[3])
                 : "r"(a[0]), "r"(a[1]), "r"(a[2]), "r"(a[3]), "r"(b[0]), "r"(b[1]));
}
__device__ __forceinline__ unsigned pack_h2(float v0, float v1) {   // v0 -> low half
    half2 h = __floats2half2_rn(v0, v1);
    return *(unsigned*)&h;
}
__device__ __forceinline__ void sts32(unsigned addr, unsigned v) {
    asm volatile("st.shared.b32 [%0], %1;" :: "r"(addr), "r"(v) : "memory");
}
__device__ __forceinline__ unsigned lds32(unsigned addr) {
    unsigned v;
    asm volatile("ld.shared.b32 %0, [%1];" : "=r"(v) : "r"(addr));
    return v;
}
__device__ __forceinline__ void sts_zero16(unsigned addr) {
    asm volatile("st.shared.v4.b32 [%0], {%1,%1,%1,%1};" :: "r"(addr), "r"(0u) : "memory");
}
// async 24KB weight image copy (1536 x 16B) + commit one group
__device__ __forceinline__ void weights_async(unsigned dst, const unsigned char* src, int tid) {
    for (int e = tid; e < 1536; e += NTHR)
        asm volatile("cp.async.cg.shared.global [%0], [%1], 16;"
                     :: "r"(dst + e * 16), "l"(src + (size_t)e * 16) : "memory");
    asm volatile("cp.async.commit_group;" ::: "memory");
}
#define CP_WAIT(n) asm volatile("cp.async.wait_group %0;" :: "n"(n) : "memory")

// ---------------- prep: fold BN, fp16 weights, pre-swizzle ----------------
// conv_w src: [blk][l][O][I][K]; image per (b3l, tap): [o row][i col] fp16,
// 128B rows, chunk-swizzle: chunk16 ^= (o & 7).
__global__ void prep_kernel(const float* __restrict__ cw, const float* __restrict__ gam,
                            const float* __restrict__ bet, const float* __restrict__ mn,
                            const float* __restrict__ vr) {
    int t = blockIdx.x * blockDim.x + threadIdx.x;
    const int NW = NBLK * 3 * 3 * 64 * 64;
    if (t < NW) {
        int i   = t & 63;
        int o   = (t >> 6) & 63;
        int tap = (t >> 12) % 3;
        int b3l = t / 12288;
        int ch  = b3l * 64 + o;
        float sc = gam[ch] * rsqrtf(vr[ch] + EPS);
        float v  = cw[(((size_t)b3l * 64 + o) * 64 + i) * 3 + tap] * sc;
        unsigned off = (unsigned)(o * 128 + (((i >> 3) ^ (o & 7)) << 4) + ((i & 7) << 1));
        size_t ib = (size_t)(b3l * 3 + tap) * 8192;
        *(unsigned short*)(g_wb + ib + off) = __half_as_ushort(__float2half_rn(v));
    }
    if (t < NBLK * 3 * 64) {
        float sc = gam[t] * rsqrtf(vr[t] + EPS);
        g_bias[t] = bet[t] - mn[t] * sc;
    }
}

// ---------------- fused block kernel (one batch element per launch) ----------------
__global__ void __launch_bounds__(NTHR, 3)
block_kernel(const float* __restrict__ xin, float* __restrict__ xout,
             const void* __restrict__ idxp, int blk, int bb) {
    extern __shared__ char smem[];
    const unsigned sbase = smem_u32(smem);
    const int tid = threadIdx.x;
    const int w   = tid >> 5;
    const int lid = tid & 31;
    const int j0  = blockIdx.x * TJ;

    int* s_pa = (int*)(smem + SM_PA);

    // index dtype detect (JAX x64 off => int32 despite astype(int64))
    const unsigned* iw = (const unsigned*)idxp;
    const bool is64 = ((iw[1] | iw[3] | iw[5] | iw[7]) == 0u);
    const long long* p64 = (const long long*)idxp;
    const int*       p32 = (const int*)idxp;

    if (tid < ROWS_X) {                          // pa rows j0-3 .. j0+126 (for scatter)
        int j = j0 - 3 + tid;
        int v = 0;
        if (j >= 0 && j < NPTS)
            v = is64 ? (int)p64[(size_t)bb * NPTS + j] : p32[(size_t)bb * NPTS + j];
        s_pa[tid] = v;
    }

    // async weight staging for layer 0 (overlaps gather)
    weights_async(sbase + SM_W, g_wb + (size_t)(blk * 3 + 0) * 24576, tid);

    // gather x through the permutation -> fp16 AX tile (zero outside sequence).
    // pa read directly from global; unrolled in two MLP batches (prologue-only regs).
    {
        const float4* x4 = (const float4*)xin;
#pragma unroll
        for (int half = 0; half < 2; half++) {
            float4 v[9];
            int    on[9];
#pragma unroll
            for (int u = 0; u < 9; u++) {
                int s  = half * 9 + u;
                int e  = tid + s * NTHR;
                bool o = (s < 16) || (tid < ROWS_X * 16 - 16 * NTHR);
                int r  = e >> 4;
                int j  = j0 - 3 + r;
                bool valid = o && (j >= 0) && (j < NPTS);
                int pa = 0;
                if (valid) pa = is64 ? (int)p64[(size_t)bb * NPTS + j] : p32[(size_t)bb * NPTS + j];
                v[u] = make_float4(0.f, 0.f, 0.f, 0.f);
                if (valid) v[u] = x4[((size_t)bb * NPTS + (size_t)pa) * 16 + (e & 15)];
                on[u] = o;
            }
#pragma unroll
            for (int u = 0; u < 9; u++) {
                if (!on[u]) continue;
                int e = tid + (half * 9 + u) * NTHR;
                int r = e >> 4, c4 = e & 15;
                unsigned off = (unsigned)(r * 128 + ((((unsigned)c4 >> 1) ^ (r & 7)) << 4) + ((c4 & 1) << 3));
                *(uint2*)(smem + SM_AX + off) = make_uint2(pack_h2(v[u].x, v[u].y), pack_h2(v[u].z, v[u].w));
            }
        }
        if (tid < 32) {   // zero rows 128,129 of H0 and H1 (read-only tails)
            int buf = (tid >> 4) & 1, rr = 128 + ((tid >> 3) & 1), ch = tid & 7;
            unsigned off = (unsigned)(rr * 128 + ch * 16);
            sts_zero16(sbase + (buf ? SM_H1 : SM_H0) + off);
        }
    }
    CP_WAIT(0);                                  // layer-0 weights landed
    __syncthreads();                             // AX, s_pa, W all visible

    // 4 warps: 2 m-groups x 2 n-groups; warp tile 64 rows x 32 cols
    const int wm  = (w >> 1) * 64;
    const int wn  = (w & 1) * 32;
    const int grp = lid >> 2;          // fragment row group
    const int qd  = lid & 3;           // fragment col quad
    const int lrow = ((lid >> 3) & 1) * 8 + (lid & 7);   // ldsm row within 16-block
    const int lch  = lid >> 4;                           // ldsm chunk select (0/1)

    const float* gb = g_bias + blk * 192;

    for (int l = 0; l < 3; l++) {
        const unsigned inB  = sbase + (l == 0 ? SM_AX : (l == 1 ? SM_H0 : SM_H1));
        const unsigned outB = sbase + (l == 0 ? SM_H0 : SM_H1);
        const unsigned sW   = sbase + SM_W;

        float c[4][4][4];              // [mt][nt][frag]
#pragma unroll
        for (int nt = 0; nt < 4; nt++) {
            int cb = wn + nt * 8 + 2 * qd;
            float2 bv = __ldg((const float2*)(gb + l * 64 + cb));
#pragma unroll
            for (int mt = 0; mt < 4; mt++) {
                c[mt][nt][0] = bv.x; c[mt][nt][1] = bv.y;
                c[mt][nt][2] = bv.x; c[mt][nt][3] = bv.y;
            }
        }

#pragma unroll
        for (int tap = 0; tap < 3; tap++) {
            const unsigned wt = sW + (unsigned)tap * 8192;
#pragma unroll
            for (int kc = 0; kc < 4; kc++) {
                const int CH = 2 * kc + lch;
                unsigned a[4][4];
#pragma unroll
                for (int mt = 0; mt < 4; mt++) {
                    int R  = wm + mt * 16 + tap + lrow;
                    unsigned off = (unsigned)(R * 128 + ((CH ^ (R & 7)) << 4));
                    ldsm4(a[mt], inB + off);
                }
                unsigned b[4][2];
#pragma unroll
                for (int ng = 0; ng < 2; ng++) {
                    int O  = wn + ng * 16 + lrow;
                    unsigned off = (unsigned)(O * 128 + ((CH ^ (O & 7)) << 4));
                    unsigned r4[4];
                    ldsm4(r4, wt + off);
                    b[ng * 2][0]     = r4[0]; b[ng * 2][1]     = r4[2];
                    b[ng * 2 + 1][0] = r4[1]; b[ng * 2 + 1][1] = r4[3];
                }
#pragma unroll
                for (int mt = 0; mt < 4; mt++)
#pragma unroll
                    for (int nt = 0; nt < 4; nt++)
                        mma_fp16(c[mt][nt], a[mt], b[nt]);
            }
        }

        if (l < 2) {
            __syncthreads();   // all warps done reading W(l) before overwrite
            // prefetch next layer's weights; overlaps the epilogue below
            weights_async(sbase + SM_W, g_wb + (size_t)(blk * 3 + l + 1) * 24576, tid);

            // ---- mid epilogue: relu + boundary zero, fp16 -> out buffer ----
#pragma unroll
            for (int mt = 0; mt < 4; mt++)
#pragma unroll
                for (int h = 0; h < 2; h++) {
                    int row = wm + mt * 16 + h * 8 + grp;
                    int pos = j0 - 2 + l + row;
                    bool valid = (unsigned)pos < (unsigned)NPTS;
#pragma unroll
                    for (int nt = 0; nt < 4; nt++) {
                        float v0 = c[mt][nt][h * 2];
                        float v1 = c[mt][nt][h * 2 + 1];
                        v0 = valid ? fmaxf(v0, 0.f) : 0.f;
                        v1 = valid ? fmaxf(v1, 0.f) : 0.f;
                        int cb = wn + nt * 8 + 2 * qd;
                        unsigned off = (unsigned)(row * 128 + (((cb >> 3) ^ (row & 7)) << 4) + ((cb & 7) << 1));
                        sts32(outB + off, pack_h2(v0, v1));
                    }
                }
            CP_WAIT(0);        // next layer's weights landed
            __syncthreads();   // epilogue H writes + W visible
        } else {
            // ---- final epilogue: + residual(fp16 x from AX) + relu, scatter ----
#pragma unroll
            for (int mt = 0; mt < 4; mt++)
#pragma unroll
                for (int h = 0; h < 2; h++) {
                    int row = wm + mt * 16 + h * 8 + grp;
                    if (row >= TJ) continue;
                    int pos = j0 + row;
                    if (pos >= NPTS) continue;
                    size_t obase = ((size_t)bb * NPTS + (size_t)s_pa[row + 3]) * 64;
                    int xr = row + 3;   // AX row holding x[j0+row]
#pragma unroll
                    for (int nt = 0; nt < 4; nt++) {
                        int cb = wn + nt * 8 + 2 * qd;
                        unsigned xoff = (unsigned)(xr * 128 + (((cb >> 3) ^ (xr & 7)) << 4) + ((cb & 7) << 1));
                        unsigned xb = lds32(sbase + SM_AX + xoff);
                        float2 xv = __half22float2(*(half2*)&xb);
                        float v0 = fmaxf(c[mt][nt][h * 2]     + xv.x, 0.f);
                        float v1 = fmaxf(c[mt][nt][h * 2 + 1] + xv.y, 0.f);
                        *(float2*)(xout + obase + cb) = make_float2(v0, v1);
                    }
                }
        }
    }
}

// ---------------- launch: per-batch fork-join (overlap kernel drains) ----------------
extern "C" void kernel_launch(void* const* d_in, const int* in_sizes, int n_in,
                              void* d_out, int out_size) {
    (void)in_sizes; (void)n_in; (void)out_size;
    const float* x   = (const float*)d_in[0];
    const void*  pa1 = d_in[1];
    // d_in[2] = idx_re_1 (unused: re is the inverse of pa, folded into scatter)
    const void*  pa2 = d_in[3];
    // d_in[4] = idx_re_2 (unused)
    const float* cw  = (const float*)d_in[5];
    const float* gam = (const float*)d_in[6];
    const float* bet = (const float*)d_in[7];
    const float* mn  = (const float*)d_in[8];
    const float* vr  = (const float*)d_in[9];
    float* out = (float*)d_out;

    float* mid = nullptr;
    cudaGetSymbolAddress((void**)&mid, g_mid);

    static cudaStream_t s1 = nullptr, s2 = nullptr;
    static cudaEvent_t  e0 = nullptr, e1 = nullptr, e2 = nullptr;
    static int attr_done = 0;
    if (!attr_done) {
        cudaFuncSetAttribute(block_kernel, cudaFuncAttributeMaxDynamicSharedMemorySize,
                             SMEM_BYTES);
        cudaStreamCreateWithFlags(&s1, cudaStreamNonBlocking);
        cudaStreamCreateWithFlags(&s2, cudaStreamNonBlocking);
        cudaEventCreateWithFlags(&e0, cudaEventDisableTiming);
        cudaEventCreateWithFlags(&e1, cudaEventDisableTiming);
        cudaEventCreateWithFlags(&e2, cudaEventDisableTiming);
        attr_done = 1;
    }

    const int NPREP = NBLK * 3 * 3 * 64 * 64;
    prep_kernel<<<(NPREP + 255) / 256, 256>>>(cw, gam, bet, mn, vr);

    // fork: two independent per-batch chains
    cudaEventRecord(e0, 0);
    cudaStreamWaitEvent(s1, e0, 0);
    cudaStreamWaitEvent(s2, e0, 0);

    dim3 grid(NTILE, 1);
    block_kernel<<<grid, NTHR, SMEM_BYTES, s1>>>(x,   mid, pa1, 0, 0);
    block_kernel<<<grid, NTHR, SMEM_BYTES, s1>>>(mid, out, pa2, 1, 0);
    block_kernel<<<grid, NTHR, SMEM_BYTES, s2>>>(x,   mid, pa1, 0, 1);
    block_kernel<<<grid, NTHR, SMEM_BYTES, s2>>>(mid, out, pa2, 1, 1);

    // join back to the captured origin stream
    cudaEventRecord(e1, s1);
    cudaEventRecord(e2, s2);
    cudaStreamWaitEvent(0, e1, 0);
    cudaStreamWaitEvent(0, e2, 0);
}